// round 1
// baseline (speedup 1.0000x reference)
#include <cuda_runtime.h>
#include <math.h>

// Problem dims (fixed by the dataset)
#define N_Q    2048
#define M_KV   4096
#define DMODEL 1024
#define NHEADS 16
#define DHEAD  64
#define DFF    4096
#define DOUT   1000

// ---------------- scratch (device globals; no allocation allowed) ----------------
__device__ float g_Q [N_Q  * DMODEL];
__device__ float g_K [M_KV * DMODEL];
__device__ float g_V [M_KV * DMODEL];
__device__ float g_S [(size_t)NHEADS * N_Q * M_KV];   // 512 MB logits / probs
__device__ float g_O [N_Q  * DMODEL];
__device__ float g_AO[N_Q  * DMODEL];
__device__ float g_FIN[N_Q * 2 * DMODEL];
__device__ float g_H [N_Q  * DFF];

// ---------------- packed f32x2 FMA helpers (sm_100+/sm_103a) ----------------
__device__ __forceinline__ unsigned long long pack2(float x, float y) {
    unsigned long long r;
    asm("mov.b64 %0, {%1, %2};" : "=l"(r) : "f"(x), "f"(y));
    return r;
}
__device__ __forceinline__ void unpack2(unsigned long long v, float &x, float &y) {
    asm("mov.b64 {%0, %1}, %2;" : "=f"(x), "=f"(y) : "l"(v));
}
__device__ __forceinline__ void ffma2(unsigned long long &c,
                                      unsigned long long a,
                                      unsigned long long b) {
    asm("fma.rn.f32x2 %0, %1, %2, %0;" : "+l"(c) : "l"(a), "l"(b));
}

// ---------------- generic tiled GEMM:  C = alpha * A @ op(B) + bias (+ReLU) ----------------
// BT=true : B is [N, K] row-major (NT form, C[m,n] += A[m,k]*B[n,k])
// BT=false: B is [K, N] row-major (NN form, C[m,n] += A[m,k]*B[k,n])
template<int BM, int BN, int BK, int TM, int TN, bool BT, bool RELU>
__global__ __launch_bounds__((BM/TM)*(BN/TN))
void gemm_kernel(int M, int N, int K,
                 const float* __restrict__ A, int lda, long long sAz,
                 const float* __restrict__ B, int ldb, long long sBz,
                 float*       __restrict__ C, int ldc, long long sCz,
                 const float* __restrict__ bias, float alpha)
{
    constexpr int THREADS = (BM/TM)*(BN/TN);
    A += (long long)blockIdx.z * sAz;
    B += (long long)blockIdx.z * sBz;
    C += (long long)blockIdx.z * sCz;

    __shared__ float As[BK][BM + 4];
    __shared__ float Bs[BK][BN + 4];

    const int tid  = threadIdx.x;
    const int tx   = tid % (BN/TN);
    const int ty   = tid / (BN/TN);
    const int row0 = blockIdx.y * BM;
    const int col0 = blockIdx.x * BN;

    unsigned long long acc[TM][TN/2];
    #pragma unroll
    for (int i = 0; i < TM; i++)
        #pragma unroll
        for (int j = 0; j < TN/2; j++) acc[i][j] = pack2(0.f, 0.f);

    for (int k0 = 0; k0 < K; k0 += BK) {
        // ---- load A tile (BM x BK), row-major, vectorized ----
        constexpr int AV = (BM*BK)/(THREADS*4);
        #pragma unroll
        for (int v = 0; v < AV; v++) {
            int idx = (tid + v*THREADS) * 4;
            int r   = idx / BK;
            int kk  = idx % BK;
            float4 t = make_float4(0.f, 0.f, 0.f, 0.f);
            int gr = row0 + r;
            if (gr < M)
                t = *reinterpret_cast<const float4*>(A + (long long)gr*lda + k0 + kk);
            As[kk+0][r] = t.x; As[kk+1][r] = t.y; As[kk+2][r] = t.z; As[kk+3][r] = t.w;
        }
        // ---- load B tile ----
        constexpr int BV = (BN*BK)/(THREADS*4);
        #pragma unroll
        for (int v = 0; v < BV; v++) {
            int idx = (tid + v*THREADS) * 4;
            if (BT) {
                int n  = idx / BK;
                int kk = idx % BK;
                float4 t = make_float4(0.f, 0.f, 0.f, 0.f);
                int gc = col0 + n;
                if (gc < N)
                    t = *reinterpret_cast<const float4*>(B + (long long)gc*ldb + k0 + kk);
                Bs[kk+0][n] = t.x; Bs[kk+1][n] = t.y; Bs[kk+2][n] = t.z; Bs[kk+3][n] = t.w;
            } else {
                int kk = idx / BN;
                int n  = idx % BN;
                // NN path only used with exact tiling (PV: N=64, BN=64) -> no guard needed
                float4 t = *reinterpret_cast<const float4*>(B + (long long)(k0+kk)*ldb + col0 + n);
                *reinterpret_cast<float4*>(&Bs[kk][n]) = t;
            }
        }
        __syncthreads();

        // ---- compute ----
        #pragma unroll
        for (int kk = 0; kk < BK; kk++) {
            float a[TM];
            unsigned long long b2[TN/2];
            #pragma unroll
            for (int i = 0; i < TM; i += 4) {
                float4 t = *reinterpret_cast<const float4*>(&As[kk][ty*TM + i]);
                a[i] = t.x; a[i+1] = t.y; a[i+2] = t.z; a[i+3] = t.w;
            }
            #pragma unroll
            for (int j = 0; j < TN; j += 4) {
                float4 t = *reinterpret_cast<const float4*>(&Bs[kk][tx*TN + j]);
                b2[j/2]     = pack2(t.x, t.y);
                b2[j/2 + 1] = pack2(t.z, t.w);
            }
            #pragma unroll
            for (int i = 0; i < TM; i++) {
                unsigned long long ai = pack2(a[i], a[i]);
                #pragma unroll
                for (int j = 0; j < TN/2; j++) ffma2(acc[i][j], ai, b2[j]);
            }
        }
        __syncthreads();
    }

    // ---- epilogue ----
    #pragma unroll
    for (int i = 0; i < TM; i++) {
        int gr = row0 + ty*TM + i;
        if (gr >= M) continue;
        #pragma unroll
        for (int j = 0; j < TN/2; j++) {
            int gc = col0 + tx*TN + j*2;
            float r0, r1;
            unpack2(acc[i][j], r0, r1);
            r0 *= alpha; r1 *= alpha;
            if (bias) {
                if (gc     < N) r0 += bias[gc];
                if (gc + 1 < N) r1 += bias[gc + 1];
            }
            if (RELU) { r0 = fmaxf(r0, 0.f); r1 = fmaxf(r1, 0.f); }
            if (gc     < N) C[(long long)gr*ldc + gc    ] = r0;
            if (gc + 1 < N) C[(long long)gr*ldc + gc + 1] = r1;
        }
    }
}

// ---------------- sparsemax: one block per row of 4096 ----------------
__device__ __forceinline__ float warp_sum(float v) {
    #pragma unroll
    for (int o = 16; o > 0; o >>= 1) v += __shfl_xor_sync(0xffffffffu, v, o);
    return v;
}
__device__ __forceinline__ float warp_max(float v) {
    #pragma unroll
    for (int o = 16; o > 0; o >>= 1) v = fmaxf(v, __shfl_xor_sync(0xffffffffu, v, o));
    return v;
}

__global__ __launch_bounds__(256)
void sparsemax_kernel(float* __restrict__ S)
{
    const long long row = blockIdx.x;
    float* z = S + row * (long long)M_KV;
    const int tid = threadIdx.x;

    float v[16];
    #pragma unroll
    for (int i = 0; i < 16; i++) v[i] = z[tid + i*256];

    __shared__ float red_s[8];
    __shared__ float red_c[8];
    __shared__ float s_tau, s_delta;

    // row max
    float m = v[0];
    #pragma unroll
    for (int i = 1; i < 16; i++) m = fmaxf(m, v[i]);
    m = warp_max(m);
    const int w = tid >> 5, lane = tid & 31;
    if (lane == 0) red_s[w] = m;
    __syncthreads();
    if (tid == 0) {
        float mm = red_s[0];
        #pragma unroll
        for (int i = 1; i < 8; i++) mm = fmaxf(mm, red_s[i]);
        s_tau = mm - 1.0f;   // f(tau0) >= 0 guaranteed
    }
    __syncthreads();
    float tau = s_tau;

    // Newton on f(tau) = sum(max(z - tau, 0)) - 1 (convex, piecewise linear):
    // finitely convergent from the left with f >= 0 at every iterate.
    for (int it = 0; it < 64; ++it) {
        float s = 0.f, c = 0.f;
        #pragma unroll
        for (int i = 0; i < 16; i++) {
            float d = v[i] - tau;
            if (d > 0.f) { s += d; c += 1.f; }
        }
        s = warp_sum(s);
        c = warp_sum(c);
        if (lane == 0) { red_s[w] = s; red_c[w] = c; }
        __syncthreads();
        if (tid == 0) {
            float St = 0.f, Ct = 0.f;
            #pragma unroll
            for (int i = 0; i < 8; i++) { St += red_s[i]; Ct += red_c[i]; }
            float delta = (St - 1.0f) / fmaxf(Ct, 1.0f);
            s_tau   = tau + delta;
            s_delta = delta;
        }
        __syncthreads();
        tau = s_tau;
        float d = s_delta;
        __syncthreads();
        if (fabsf(d) < 1e-9f) break;
    }

    #pragma unroll
    for (int i = 0; i < 16; i++) z[tid + i*256] = fmaxf(v[i] - tau, 0.f);
}

// ---------------- concat [enc | AO] -> FIN ----------------
__global__ __launch_bounds__(256)
void concat_kernel(const float* __restrict__ enc,
                   const float* __restrict__ ao,
                   float* __restrict__ fin)
{
    int i = blockIdx.x * 256 + threadIdx.x;   // over N_Q * 2048
    int n = i >> 11;
    int c = i & 2047;
    fin[i] = (c < DMODEL) ? enc[n*DMODEL + c] : ao[n*DMODEL + c - DMODEL];
}

// ---------------- host launcher ----------------
extern "C" void kernel_launch(void* const* d_in, const int* in_sizes, int n_in,
                              void* d_out, int out_size)
{
    const float* enc = (const float*)d_in[0];
    const float* mem = (const float*)d_in[1];
    const float* Wq  = (const float*)d_in[2];
    const float* bq  = (const float*)d_in[3];
    const float* Wk  = (const float*)d_in[4];
    const float* bk  = (const float*)d_in[5];
    const float* Wv  = (const float*)d_in[6];
    const float* bv  = (const float*)d_in[7];
    const float* Wo  = (const float*)d_in[8];
    const float* bo  = (const float*)d_in[9];
    const float* W1  = (const float*)d_in[10];
    const float* b1  = (const float*)d_in[11];
    const float* W2  = (const float*)d_in[12];
    const float* b2  = (const float*)d_in[13];
    float* out = (float*)d_out;

    float *pQ, *pK, *pV, *pS, *pO, *pAO, *pFIN, *pH;
    cudaGetSymbolAddress((void**)&pQ,  g_Q);
    cudaGetSymbolAddress((void**)&pK,  g_K);
    cudaGetSymbolAddress((void**)&pV,  g_V);
    cudaGetSymbolAddress((void**)&pS,  g_S);
    cudaGetSymbolAddress((void**)&pO,  g_O);
    cudaGetSymbolAddress((void**)&pAO, g_AO);
    cudaGetSymbolAddress((void**)&pFIN,g_FIN);
    cudaGetSymbolAddress((void**)&pH,  g_H);

    dim3 blk(256);

    // Q = enc @ Wq^T + bq          [2048, 1024]
    gemm_kernel<128,128,16,8,8,true,false>
        <<<dim3(DMODEL/128, N_Q/128, 1), blk>>>(
        N_Q, DMODEL, DMODEL, enc, DMODEL, 0, Wq, DMODEL, 0, pQ, DMODEL, 0, bq, 1.0f);

    // K = mem @ Wk^T + bk          [4096, 1024]
    gemm_kernel<128,128,16,8,8,true,false>
        <<<dim3(DMODEL/128, M_KV/128, 1), blk>>>(
        M_KV, DMODEL, DMODEL, mem, DMODEL, 0, Wk, DMODEL, 0, pK, DMODEL, 0, bk, 1.0f);

    // V = mem @ Wv^T + bv          [4096, 1024]
    gemm_kernel<128,128,16,8,8,true,false>
        <<<dim3(DMODEL/128, M_KV/128, 1), blk>>>(
        M_KV, DMODEL, DMODEL, mem, DMODEL, 0, Wv, DMODEL, 0, pV, DMODEL, 0, bv, 1.0f);

    // S[h] = (Q_h @ K_h^T) / 32    [16, 2048, 4096]
    gemm_kernel<128,128,16,8,8,true,false>
        <<<dim3(M_KV/128, N_Q/128, NHEADS), blk>>>(
        N_Q, M_KV, DHEAD,
        pQ, DMODEL, (long long)DHEAD,
        pK, DMODEL, (long long)DHEAD,
        pS, M_KV,   (long long)N_Q * M_KV,
        nullptr, 0.03125f);

    // sparsemax over each row of 4096 (in place)
    sparsemax_kernel<<<NHEADS * N_Q, blk>>>(pS);

    // O[:, h*64:(h+1)*64] = P_h @ V_h     (NN GEMM, N = 64)
    gemm_kernel<64,64,16,4,4,false,false>
        <<<dim3(1, N_Q/64, NHEADS), blk>>>(
        N_Q, DHEAD, M_KV,
        pS, M_KV,  (long long)N_Q * M_KV,
        pV, DMODEL,(long long)DHEAD,
        pO, DMODEL,(long long)DHEAD,
        nullptr, 1.0f);

    // AO = O @ Wo^T + bo           [2048, 1024]
    gemm_kernel<64,64,16,4,4,true,false>
        <<<dim3(DMODEL/64, N_Q/64, 1), blk>>>(
        N_Q, DMODEL, DMODEL, pO, DMODEL, 0, Wo, DMODEL, 0, pAO, DMODEL, 0, bo, 1.0f);

    // FIN = [enc | AO]             [2048, 2048]
    concat_kernel<<<(N_Q * 2 * DMODEL) / 256, blk>>>(enc, pAO, pFIN);

    // H = relu(FIN @ W1^T + b1)    [2048, 4096]
    gemm_kernel<128,128,16,8,8,true,true>
        <<<dim3(DFF/128, N_Q/128, 1), blk>>>(
        N_Q, DFF, 2*DMODEL, pFIN, 2*DMODEL, 0, W1, 2*DMODEL, 0, pH, DFF, 0, b1, 1.0f);

    // OUT = H @ W2^T + b2          [2048, 1000]
    gemm_kernel<64,64,16,4,4,true,false>
        <<<dim3((DOUT + 63)/64, N_Q/64, 1), blk>>>(
        N_Q, DOUT, DFF, pH, DFF, 0, W2, DFF, 0, out, DOUT, 0, b2, 1.0f);
}

// round 3
// speedup vs baseline: 1.5586x; 1.5586x over previous
#include <cuda_runtime.h>
#include <cuda_bf16.h>
#include <cstdint>
#include <math.h>

// Problem dims (fixed by the dataset)
#define N_Q    2048
#define M_KV   4096
#define DMODEL 1024
#define NHEADS 16
#define DHEAD  64
#define DFF    4096
#define DOUT   1000

// ---------------- scratch (device globals; no allocation allowed) ----------------
__device__ float g_Q  [N_Q  * DMODEL];
__device__ float g_K  [M_KV * DMODEL];
__device__ float g_V  [M_KV * DMODEL];
__device__ float g_S  [(size_t)NHEADS * N_Q * M_KV];   // 512 MB logits / probs
__device__ float g_O  [N_Q  * DMODEL];
__device__ float g_AO [N_Q  * DMODEL];
__device__ float g_FIN[N_Q * 2 * DMODEL];
__device__ float g_H  [N_Q  * DFF];

// ---------------- helpers ----------------
__device__ __forceinline__ uint32_t smem_u32(const void* p) {
    uint32_t a;
    asm("{ .reg .u64 t; cvta.to.shared.u64 t, %1; cvt.u32.u64 %0, t; }" : "=r"(a) : "l"(p));
    return a;
}
__device__ __forceinline__ void ldmx4(uint32_t* r, uint32_t a) {
    asm volatile("ldmatrix.sync.aligned.m8n8.x4.shared.b16 {%0,%1,%2,%3}, [%4];"
                 : "=r"(r[0]), "=r"(r[1]), "=r"(r[2]), "=r"(r[3]) : "r"(a));
}
__device__ __forceinline__ void mma_bf16(float* d, const uint32_t* a, uint32_t b0, uint32_t b1) {
    asm volatile("mma.sync.aligned.m16n8k16.row.col.f32.bf16.bf16.f32 "
                 "{%0,%1,%2,%3}, {%4,%5,%6,%7}, {%8,%9}, {%0,%1,%2,%3};"
                 : "+f"(d[0]), "+f"(d[1]), "+f"(d[2]), "+f"(d[3])
                 : "r"(a[0]), "r"(a[1]), "r"(a[2]), "r"(a[3]), "r"(b0), "r"(b1));
}
// fp32 pair -> bf16 hi + bf16 residual(lo), packed as b32
__device__ __forceinline__ void split_pair(float a, float b, uint32_t& h, uint32_t& l) {
    __nv_bfloat162 hh = __floats2bfloat162_rn(a, b);
    float2 hf = __bfloat1622float2(hh);
    __nv_bfloat162 ll = __floats2bfloat162_rn(a - hf.x, b - hf.y);
    h = *reinterpret_cast<uint32_t*>(&hh);
    l = *reinterpret_cast<uint32_t*>(&ll);
}

// ====================== mma.sync split-bf16 GEMM ======================
// C = alpha * A @ op(B) + bias (+ReLU)
// BTRANS=false: NT, B is [N,K] row-major.  BTRANS=true: NN, B is [K,N] row-major.
// Batch via blockIdx.z (sAz/sBz/sCz element strides).
template<int BM, int BN, int WM, int WN, bool BTRANS, bool RELU, bool NGUARD>
__global__ __launch_bounds__(256, 2)
void mma_gemm(int M, int N, int K,
              const float* __restrict__ A, int lda, long long sAz,
              const float* __restrict__ B, int ldb, long long sBz,
              float*       __restrict__ C, long long ldc, long long sCz,
              const float* __restrict__ bias, float alpha)
{
    constexpr int BK  = 32;
    constexpr int BKP = 40;                 // padded row: 80 bytes, conflict-free ldmatrix
    constexpr int WNC = BN / WN;            // warps along n
    constexpr int MI  = WM / 16;            // m16 atoms per warp
    constexpr int NI2 = WN / 16;            // ldmatrix x4 groups along n
    constexpr int NA  = WN / 8;             // n8 atoms per warp

    extern __shared__ __align__(16) char smem[];
    __nv_bfloat16* sAh = reinterpret_cast<__nv_bfloat16*>(smem);
    __nv_bfloat16* sAl = sAh + BM * BKP;
    __nv_bfloat16* sBh = sAl + BM * BKP;
    __nv_bfloat16* sBl = sBh + BN * BKP;

    const int tid  = threadIdx.x;
    const int wid  = tid >> 5;
    const int lane = tid & 31;
    A += (long long)blockIdx.z * sAz;
    B += (long long)blockIdx.z * sBz;
    C += (long long)blockIdx.z * sCz;
    const int row0 = blockIdx.y * BM;
    const int col0 = blockIdx.x * BN;
    const int wm0 = (wid / WNC) * WM;
    const int wn0 = (wid % WNC) * WN;

    const uint32_t uAh = smem_u32(sAh), uAl = smem_u32(sAl);
    const uint32_t uBh = smem_u32(sBh), uBl = smem_u32(sBl);
    const int lr = lane & 15, lc = (lane >> 4) * 8;

    float acc[MI][NA][4];
    #pragma unroll
    for (int i = 0; i < MI; i++)
        #pragma unroll
        for (int j = 0; j < NA; j++)
            #pragma unroll
            for (int q = 0; q < 4; q++) acc[i][j][q] = 0.f;

    for (int kt = 0; kt < K; kt += BK) {
        // ---- A tile: BM x 32 fp32, split to bf16 hi/lo ----
        #pragma unroll
        for (int it = 0; it < BM / 32; it++) {
            int idx = tid + it * 256;
            int r = idx >> 3, c = (idx & 7) * 4;
            float4 v = *reinterpret_cast<const float4*>(A + (long long)(row0 + r) * lda + kt + c);
            uint32_t h0, l0, h1, l1;
            split_pair(v.x, v.y, h0, l0);
            split_pair(v.z, v.w, h1, l1);
            int so = r * BKP + c;
            *reinterpret_cast<uint2*>(&sAh[so]) = make_uint2(h0, h1);
            *reinterpret_cast<uint2*>(&sAl[so]) = make_uint2(l0, l1);
        }
        // ---- B tile ----
        if (!BTRANS) {
            #pragma unroll
            for (int it = 0; it < BN / 32; it++) {
                int idx = tid + it * 256;
                int r = idx >> 3, c = (idx & 7) * 4;
                float4 v = make_float4(0.f, 0.f, 0.f, 0.f);
                if (!NGUARD || (col0 + r) < N)
                    v = *reinterpret_cast<const float4*>(B + (long long)(col0 + r) * ldb + kt + c);
                uint32_t h0, l0, h1, l1;
                split_pair(v.x, v.y, h0, l0);
                split_pair(v.z, v.w, h1, l1);
                int so = r * BKP + c;
                *reinterpret_cast<uint2*>(&sBh[so]) = make_uint2(h0, h1);
                *reinterpret_cast<uint2*>(&sBl[so]) = make_uint2(l0, l1);
            }
        } else {
            // B is [K,N]: read rows of k, store transposed [n][k]
            #pragma unroll
            for (int it = 0; it < (BK * BN) / (4 * 256); it++) {
                int idx = tid + it * 256;
                int rk = idx / (BN / 4), cn = (idx % (BN / 4)) * 4;
                float4 v = *reinterpret_cast<const float4*>(B + (long long)(kt + rk) * ldb + col0 + cn);
                float vv[4] = {v.x, v.y, v.z, v.w};
                #pragma unroll
                for (int j = 0; j < 4; j++) {
                    __nv_bfloat16 h = __float2bfloat16_rn(vv[j]);
                    __nv_bfloat16 l = __float2bfloat16_rn(vv[j] - __bfloat162float(h));
                    sBh[(cn + j) * BKP + rk] = h;
                    sBl[(cn + j) * BKP + rk] = l;
                }
            }
        }
        __syncthreads();

        // ---- compute: two k16 steps ----
        #pragma unroll
        for (int kk = 0; kk < BK; kk += 16) {
            uint32_t bh[NI2][4], bl[NI2][4];
            #pragma unroll
            for (int ni = 0; ni < NI2; ni++) {
                uint32_t off = ((wn0 + ni * 16 + lr) * BKP + kk + lc) * 2;
                ldmx4(bh[ni], uBh + off);
                ldmx4(bl[ni], uBl + off);
            }
            #pragma unroll
            for (int mi = 0; mi < MI; mi++) {
                uint32_t ah[4], al[4];
                uint32_t off = ((wm0 + mi * 16 + lr) * BKP + kk + lc) * 2;
                ldmx4(ah, uAh + off);
                ldmx4(al, uAl + off);
                #pragma unroll
                for (int na = 0; na < NA; na++) {
                    int ni = na >> 1, sel = na & 1;
                    uint32_t b0h = bh[ni][sel], b1h = bh[ni][sel + 2];
                    mma_bf16(acc[mi][na], ah, b0h, b1h);
                    mma_bf16(acc[mi][na], al, b0h, b1h);
                    mma_bf16(acc[mi][na], ah, bl[ni][sel], bl[ni][sel + 2]);
                }
            }
        }
        __syncthreads();
    }

    // ---------------- epilogue ----------------
    const int lr4 = lane >> 2, lc2 = (lane & 3) * 2;
    #pragma unroll
    for (int mi = 0; mi < MI; mi++) {
        #pragma unroll
        for (int na = 0; na < NA; na++) {
            float* d = acc[mi][na];
            int col = col0 + wn0 + na * 8 + lc2;
            int r0 = row0 + wm0 + mi * 16 + lr4;
            float bb0 = 0.f, bb1 = 0.f;
            if (bias) {
                if (!NGUARD || col     < N) bb0 = bias[col];
                if (!NGUARD || col + 1 < N) bb1 = bias[col + 1];
            }
            float v0 = d[0] * alpha + bb0, v1 = d[1] * alpha + bb1;
            float v2 = d[2] * alpha + bb0, v3 = d[3] * alpha + bb1;
            if (RELU) {
                v0 = fmaxf(v0, 0.f); v1 = fmaxf(v1, 0.f);
                v2 = fmaxf(v2, 0.f); v3 = fmaxf(v3, 0.f);
            }
            long long b0i = (long long)r0 * ldc + col;
            long long b1i = (long long)(r0 + 8) * ldc + col;
            if (!NGUARD || col + 1 < N) {
                *reinterpret_cast<float2*>(C + b0i) = make_float2(v0, v1);
                *reinterpret_cast<float2*>(C + b1i) = make_float2(v2, v3);
            } else if (col < N) {
                C[b0i] = v0;
                C[b1i] = v2;
            }
        }
    }
}

// ---------------- sparsemax: one block per row of 4096 ----------------
__device__ __forceinline__ float warp_sum(float v) {
    #pragma unroll
    for (int o = 16; o > 0; o >>= 1) v += __shfl_xor_sync(0xffffffffu, v, o);
    return v;
}
__device__ __forceinline__ float warp_max(float v) {
    #pragma unroll
    for (int o = 16; o > 0; o >>= 1) v = fmaxf(v, __shfl_xor_sync(0xffffffffu, v, o));
    return v;
}
__global__ __launch_bounds__(256)
void sparsemax_kernel(float* __restrict__ S)
{
    const long long row = blockIdx.x;
    float* z = S + row * (long long)M_KV;
    const int tid = threadIdx.x;
    float v[16];
    #pragma unroll
    for (int i = 0; i < 16; i++) v[i] = z[tid + i * 256];

    __shared__ float red_s[8];
    __shared__ float red_c[8];
    __shared__ float s_tau, s_delta;

    float m = v[0];
    #pragma unroll
    for (int i = 1; i < 16; i++) m = fmaxf(m, v[i]);
    m = warp_max(m);
    const int w = tid >> 5, lane = tid & 31;
    if (lane == 0) red_s[w] = m;
    __syncthreads();
    if (tid == 0) {
        float mm = red_s[0];
        #pragma unroll
        for (int i = 1; i < 8; i++) mm = fmaxf(mm, red_s[i]);
        s_tau = mm - 1.0f;
    }
    __syncthreads();
    float tau = s_tau;

    for (int it = 0; it < 64; ++it) {
        float s = 0.f, c = 0.f;
        #pragma unroll
        for (int i = 0; i < 16; i++) {
            float d = v[i] - tau;
            if (d > 0.f) { s += d; c += 1.f; }
        }
        s = warp_sum(s); c = warp_sum(c);
        if (lane == 0) { red_s[w] = s; red_c[w] = c; }
        __syncthreads();
        if (tid == 0) {
            float St = 0.f, Ct = 0.f;
            #pragma unroll
            for (int i = 0; i < 8; i++) { St += red_s[i]; Ct += red_c[i]; }
            float delta = (St - 1.0f) / fmaxf(Ct, 1.0f);
            s_tau = tau + delta;
            s_delta = delta;
        }
        __syncthreads();
        tau = s_tau;
        float d = s_delta;
        __syncthreads();
        if (fabsf(d) < 1e-9f) break;
    }
    #pragma unroll
    for (int i = 0; i < 16; i++) z[tid + i * 256] = fmaxf(v[i] - tau, 0.f);
}

// ---------------- concat [enc | AO] -> FIN ----------------
__global__ __launch_bounds__(256)
void concat_kernel(const float* __restrict__ enc,
                   const float* __restrict__ ao,
                   float* __restrict__ fin)
{
    int i = blockIdx.x * 256 + threadIdx.x;
    int n = i >> 11;
    int c = i & 2047;
    fin[i] = (c < DMODEL) ? enc[n * DMODEL + c] : ao[n * DMODEL + c - DMODEL];
}

// ---------------- host launcher ----------------
extern "C" void kernel_launch(void* const* d_in, const int* in_sizes, int n_in,
                              void* d_out, int out_size)
{
    const float* enc = (const float*)d_in[0];
    const float* mem = (const float*)d_in[1];
    const float* Wq  = (const float*)d_in[2];
    const float* bq  = (const float*)d_in[3];
    const float* Wk  = (const float*)d_in[4];
    const float* bk  = (const float*)d_in[5];
    const float* Wv  = (const float*)d_in[6];
    const float* bv  = (const float*)d_in[7];
    const float* Wo  = (const float*)d_in[8];
    const float* bo  = (const float*)d_in[9];
    const float* W1  = (const float*)d_in[10];
    const float* b1  = (const float*)d_in[11];
    const float* W2  = (const float*)d_in[12];
    const float* b2  = (const float*)d_in[13];
    float* out = (float*)d_out;

    float *pQ, *pK, *pV, *pS, *pO, *pAO, *pFIN, *pH;
    cudaGetSymbolAddress((void**)&pQ,  g_Q);
    cudaGetSymbolAddress((void**)&pK,  g_K);
    cudaGetSymbolAddress((void**)&pV,  g_V);
    cudaGetSymbolAddress((void**)&pS,  g_S);
    cudaGetSymbolAddress((void**)&pO,  g_O);
    cudaGetSymbolAddress((void**)&pAO, g_AO);
    cudaGetSymbolAddress((void**)&pFIN,g_FIN);
    cudaGetSymbolAddress((void**)&pH,  g_H);

    constexpr int BKP = 40;
    const int DS_MAIN = (128 + 128) * BKP * 2 * 2;   // 40960 B
    const int DS_PV   = (128 +  64) * BKP * 2 * 2;   // 30720 B

    auto* kPlain = mma_gemm<128,128,64,32,false,false,false>;
    auto* kRelu  = mma_gemm<128,128,64,32,false,true ,false>;
    auto* kNg    = mma_gemm<128,128,64,32,false,false,true >;
    auto* kPV    = mma_gemm<128, 64,64,16,true ,false,false>;

    dim3 blk(256);

    // Q = enc @ Wq^T + bq          [2048, 1024]
    kPlain<<<dim3(DMODEL/128, N_Q/128, 1), blk, DS_MAIN>>>(
        N_Q, DMODEL, DMODEL, enc, DMODEL, 0, Wq, DMODEL, 0, pQ, DMODEL, 0, bq, 1.0f);
    // K = mem @ Wk^T + bk          [4096, 1024]
    kPlain<<<dim3(DMODEL/128, M_KV/128, 1), blk, DS_MAIN>>>(
        M_KV, DMODEL, DMODEL, mem, DMODEL, 0, Wk, DMODEL, 0, pK, DMODEL, 0, bk, 1.0f);
    // V = mem @ Wv^T + bv          [4096, 1024]
    kPlain<<<dim3(DMODEL/128, M_KV/128, 1), blk, DS_MAIN>>>(
        M_KV, DMODEL, DMODEL, mem, DMODEL, 0, Wv, DMODEL, 0, pV, DMODEL, 0, bv, 1.0f);
    // S[h] = (Q_h @ K_h^T) / 32    [16, 2048, 4096]
    kPlain<<<dim3(M_KV/128, N_Q/128, NHEADS), blk, DS_MAIN>>>(
        N_Q, M_KV, DHEAD,
        pQ, DMODEL, (long long)DHEAD,
        pK, DMODEL, (long long)DHEAD,
        pS, M_KV,   (long long)N_Q * M_KV,
        nullptr, 0.03125f);
    // sparsemax in place
    sparsemax_kernel<<<NHEADS * N_Q, blk>>>(pS);
    // O[:, h*64:(h+1)*64] = P_h @ V_h     (NN, B = V[:, h*64:(h+1)*64])
    kPV<<<dim3(1, N_Q/128, NHEADS), blk, DS_PV>>>(
        N_Q, DHEAD, M_KV,
        pS, M_KV,   (long long)N_Q * M_KV,
        pV, DMODEL, (long long)DHEAD,
        pO, DMODEL, (long long)DHEAD,
        nullptr, 1.0f);
    // AO = O @ Wo^T + bo
    kPlain<<<dim3(DMODEL/128, N_Q/128, 1), blk, DS_MAIN>>>(
        N_Q, DMODEL, DMODEL, pO, DMODEL, 0, Wo, DMODEL, 0, pAO, DMODEL, 0, bo, 1.0f);
    // FIN = [enc | AO]
    concat_kernel<<<(N_Q * 2 * DMODEL) / 256, blk>>>(enc, pAO, pFIN);
    // H = relu(FIN @ W1^T + b1)
    kRelu<<<dim3(DFF/128, N_Q/128, 1), blk, DS_MAIN>>>(
        N_Q, DFF, 2*DMODEL, pFIN, 2*DMODEL, 0, W1, 2*DMODEL, 0, pH, DFF, 0, b1, 1.0f);
    // OUT = H @ W2^T + b2          (N = 1000, guarded)
    kNg<<<dim3((DOUT + 127)/128, N_Q/128, 1), blk, DS_MAIN>>>(
        N_Q, DOUT, DFF, pH, DFF, 0, W2, DFF, 0, out, DOUT, 0, b2, 1.0f);
}

// round 4
// speedup vs baseline: 1.6503x; 1.0588x over previous
#include <cuda_runtime.h>
#include <cuda_bf16.h>
#include <cstdint>
#include <math.h>

// Problem dims (fixed by the dataset)
#define N_Q    2048
#define M_KV   4096
#define DMODEL 1024
#define NHEADS 16
#define DHEAD  64
#define DFF    4096
#define DOUT   1000

typedef __nv_bfloat16 bf16;

// ---------------- scratch (device globals; no allocation allowed) ----------------
__device__ bf16 g_FINh[N_Q * 2 * DMODEL],  g_FINl[N_Q * 2 * DMODEL];
__device__ bf16 g_memh[M_KV * DMODEL],     g_meml[M_KV * DMODEL];
__device__ bf16 g_Wqh[DMODEL * DMODEL],    g_Wql[DMODEL * DMODEL];
__device__ bf16 g_Wkh[DMODEL * DMODEL],    g_Wkl[DMODEL * DMODEL];
__device__ bf16 g_Wvh[DMODEL * DMODEL],    g_Wvl[DMODEL * DMODEL];
__device__ bf16 g_Woh[DMODEL * DMODEL],    g_Wol[DMODEL * DMODEL];
__device__ bf16 g_W1h[DFF * 2 * DMODEL],   g_W1l[DFF * 2 * DMODEL];
__device__ bf16 g_W2h[DOUT * DFF],         g_W2l[DOUT * DFF];
__device__ bf16 g_Qh[N_Q * DMODEL],        g_Ql[N_Q * DMODEL];
__device__ bf16 g_Kh[M_KV * DMODEL],       g_Kl[M_KV * DMODEL];
__device__ bf16 g_Vh[M_KV * DMODEL],       g_Vl[M_KV * DMODEL];
__device__ float g_S[(size_t)NHEADS * N_Q * M_KV];
__device__ bf16 g_Ph[(size_t)NHEADS * N_Q * M_KV], g_Pl[(size_t)NHEADS * N_Q * M_KV];
__device__ bf16 g_Oh[N_Q * DMODEL],        g_Ol[N_Q * DMODEL];
__device__ bf16 g_Hh[N_Q * DFF],           g_Hl[N_Q * DFF];

// ---------------- helpers ----------------
__device__ __forceinline__ uint32_t smem_u32(const void* p) {
    uint32_t a;
    asm("{ .reg .u64 t; cvta.to.shared.u64 t, %1; cvt.u32.u64 %0, t; }" : "=r"(a) : "l"(p));
    return a;
}
__device__ __forceinline__ void ldmx4(uint32_t* r, uint32_t a) {
    asm volatile("ldmatrix.sync.aligned.m8n8.x4.shared.b16 {%0,%1,%2,%3}, [%4];"
                 : "=r"(r[0]), "=r"(r[1]), "=r"(r[2]), "=r"(r[3]) : "r"(a));
}
__device__ __forceinline__ void mma_bf16(float* d, const uint32_t* a, uint32_t b0, uint32_t b1) {
    asm volatile("mma.sync.aligned.m16n8k16.row.col.f32.bf16.bf16.f32 "
                 "{%0,%1,%2,%3}, {%4,%5,%6,%7}, {%8,%9}, {%0,%1,%2,%3};"
                 : "+f"(d[0]), "+f"(d[1]), "+f"(d[2]), "+f"(d[3])
                 : "r"(a[0]), "r"(a[1]), "r"(a[2]), "r"(a[3]), "r"(b0), "r"(b1));
}
__device__ __forceinline__ void cpa16(uint32_t s, const void* g) {
    asm volatile("cp.async.cg.shared.global [%0], [%1], 16;" :: "r"(s), "l"(g));
}
__device__ __forceinline__ void cpa16z(uint32_t s, const void* g, bool ok) {
    int sz = ok ? 16 : 0;
    asm volatile("cp.async.cg.shared.global [%0], [%1], 16, %2;" :: "r"(s), "l"(g), "r"(sz));
}
#define CPA_COMMIT() asm volatile("cp.async.commit_group;" ::: "memory")
#define CPA_WAIT0()  asm volatile("cp.async.wait_group 0;" ::: "memory")

// split fp32 pair into packed bf16 hi + bf16 residual
__device__ __forceinline__ void split2(float a, float b, uint32_t& h, uint32_t& l) {
    __nv_bfloat162 hh = __floats2bfloat162_rn(a, b);
    float2 hf = __bfloat1622float2(hh);
    __nv_bfloat162 ll = __floats2bfloat162_rn(a - hf.x, b - hf.y);
    h = *reinterpret_cast<uint32_t*>(&hh);
    l = *reinterpret_cast<uint32_t*>(&ll);
}

// ====================== async double-buffered split-bf16 MMA GEMM ======================
// C = alpha * A @ op(B) + bias (+ReLU).  A,B pre-split bf16 hi/lo.
// BTRANS=false: NT, B[N,K] row-major. BTRANS=true: NN, B[K,N] row-major.
// EPI=0: write fp32 to Cf.  EPI=1: write split hi/lo to Chi/Clo.
template<int BM, int BN, int WM, int WN, bool BTRANS, int EPI, bool RELU, bool NGUARD>
__global__ __launch_bounds__(256, 2)
void mma_gemm(int M, int N, int K,
              const bf16* __restrict__ Ah, const bf16* __restrict__ Al, int lda, long long sAz,
              const bf16* __restrict__ Bh, const bf16* __restrict__ Bl, int ldb, long long sBz,
              float* __restrict__ Cf, bf16* __restrict__ Chi, bf16* __restrict__ Clo,
              long long ldc, long long sCz,
              const float* __restrict__ bias, float alpha)
{
    constexpr int BK = 32, BKP = 40;               // 80B pitch: 16B-aligned, ldmatrix conflict-free
    constexpr int WNC = BN / WN;
    constexpr int MI = WM / 16, NI2 = WN / 16, NA = WN / 8;
    constexpr int SA = BM * BKP, SB = BN * BKP;    // elements per array per stage
    constexpr int STAGE_BYTES = (2 * SA + 2 * SB) * 2;

    extern __shared__ __align__(16) char smem[];
    const uint32_t uS = smem_u32(smem);

    const int tid = threadIdx.x, wid = tid >> 5, lane = tid & 31;
    Ah += (long long)blockIdx.z * sAz;  Al += (long long)blockIdx.z * sAz;
    Bh += (long long)blockIdx.z * sBz;  Bl += (long long)blockIdx.z * sBz;
    const long long coff = (long long)blockIdx.z * sCz;
    const int row0 = blockIdx.y * BM;
    const int col0 = blockIdx.x * BN;
    const int wm0 = (wid / WNC) * WM;
    const int wn0 = (wid % WNC) * WN;

    float acc[MI][NA][4];
    #pragma unroll
    for (int i = 0; i < MI; i++)
        #pragma unroll
        for (int j = 0; j < NA; j++)
            #pragma unroll
            for (int q = 0; q < 4; q++) acc[i][j][q] = 0.f;

    uint4 bufBh, bufBl;                             // BTRANS prefetch regs
    const int b_rk = tid >> 3, b_cn = (tid & 7) * 8;

    auto loadA = [&](int stage, int kt) {
        uint32_t base = uS + stage * STAGE_BYTES;
        #pragma unroll
        for (int i = 0; i < (BM * 4) / 256; i++) {
            int ch = tid + i * 256, r = ch >> 2, q = ch & 3;
            cpa16(base + r * 80 + q * 16,            Ah + (size_t)(row0 + r) * lda + kt + q * 8);
            cpa16(base + SA * 2 + r * 80 + q * 16,   Al + (size_t)(row0 + r) * lda + kt + q * 8);
        }
        if (!BTRANS) {
            #pragma unroll
            for (int i = 0; i < (BN * 4) / 256; i++) {
                int ch = tid + i * 256, r = ch >> 2, q = ch & 3;
                bool ok = !NGUARD || (col0 + r) < N;
                cpa16z(base + 2 * SA * 2 + r * 80 + q * 16,
                       Bh + (size_t)(col0 + r) * ldb + kt + q * 8, ok);
                cpa16z(base + (2 * SA + SB) * 2 + r * 80 + q * 16,
                       Bl + (size_t)(col0 + r) * ldb + kt + q * 8, ok);
            }
        }
    };
    auto ldB = [&](int kt) {
        bufBh = *reinterpret_cast<const uint4*>(Bh + (size_t)(kt + b_rk) * ldb + col0 + b_cn);
        bufBl = *reinterpret_cast<const uint4*>(Bl + (size_t)(kt + b_rk) * ldb + col0 + b_cn);
    };
    auto stsB = [&](int stage) {
        bf16* sBh = reinterpret_cast<bf16*>(smem + stage * STAGE_BYTES + 2 * SA * 2);
        bf16* sBl = sBh + SB;
        bf16 th[8], tl[8];
        *reinterpret_cast<uint4*>(th) = bufBh;
        *reinterpret_cast<uint4*>(tl) = bufBl;
        #pragma unroll
        for (int j = 0; j < 8; j++) {
            sBh[(b_cn + j) * BKP + b_rk] = th[j];
            sBl[(b_cn + j) * BKP + b_rk] = tl[j];
        }
    };
    auto compute = [&](int stage) {
        uint32_t bA = uS + stage * STAGE_BYTES;
        uint32_t bAh = bA, bAl = bA + SA * 2, bBh = bA + 2 * SA * 2, bBl = bA + (2 * SA + SB) * 2;
        const int lr = lane & 15, lc = (lane >> 4) * 8;
        #pragma unroll
        for (int kk = 0; kk < BK; kk += 16) {
            uint32_t bh[NI2][4], bl[NI2][4];
            #pragma unroll
            for (int ni = 0; ni < NI2; ni++) {
                uint32_t off = (uint32_t)((wn0 + ni * 16 + lr) * 80 + (kk + lc) * 2);
                ldmx4(bh[ni], bBh + off);
                ldmx4(bl[ni], bBl + off);
            }
            #pragma unroll
            for (int mi = 0; mi < MI; mi++) {
                uint32_t ah[4], al[4];
                uint32_t off = (uint32_t)((wm0 + mi * 16 + lr) * 80 + (kk + lc) * 2);
                ldmx4(ah, bAh + off);
                ldmx4(al, bAl + off);
                #pragma unroll
                for (int na = 0; na < NA; na++) {
                    int ni = na >> 1, sel = na & 1;
                    uint32_t b0h = bh[ni][sel], b1h = bh[ni][sel + 2];
                    mma_bf16(acc[mi][na], ah, b0h, b1h);
                    mma_bf16(acc[mi][na], al, b0h, b1h);
                    mma_bf16(acc[mi][na], ah, bl[ni][sel], bl[ni][sel + 2]);
                }
            }
        }
    };

    const int tiles = K / BK;
    if (BTRANS) ldB(0);
    loadA(0, 0);
    CPA_COMMIT();
    for (int t = 0; t < tiles; t++) {
        int cur = t & 1;
        if (BTRANS) {
            stsB(cur);
            if (t + 1 < tiles) ldB((t + 1) * BK);
        }
        CPA_WAIT0();
        __syncthreads();
        if (t + 1 < tiles) loadA((t + 1) & 1, (t + 1) * BK);
        CPA_COMMIT();
        compute(cur);
    }

    // ---------------- epilogue ----------------
    const int lr4 = lane >> 2, lc2 = (lane & 3) * 2;
    #pragma unroll
    for (int mi = 0; mi < MI; mi++) {
        #pragma unroll
        for (int na = 0; na < NA; na++) {
            float* d = acc[mi][na];
            int col = col0 + wn0 + na * 8 + lc2;
            int r0 = row0 + wm0 + mi * 16 + lr4;
            float bb0 = 0.f, bb1 = 0.f;
            if (bias) {
                if (!NGUARD || col     < N) bb0 = bias[col];
                if (!NGUARD || col + 1 < N) bb1 = bias[col + 1];
            }
            float v0 = d[0] * alpha + bb0, v1 = d[1] * alpha + bb1;
            float v2 = d[2] * alpha + bb0, v3 = d[3] * alpha + bb1;
            if (RELU) {
                v0 = fmaxf(v0, 0.f); v1 = fmaxf(v1, 0.f);
                v2 = fmaxf(v2, 0.f); v3 = fmaxf(v3, 0.f);
            }
            if (EPI == 0) {
                long long b0i = (long long)r0 * ldc + col + coff;
                long long b1i = (long long)(r0 + 8) * ldc + col + coff;
                if (!NGUARD || col + 1 < N) {
                    *reinterpret_cast<float2*>(Cf + b0i) = make_float2(v0, v1);
                    *reinterpret_cast<float2*>(Cf + b1i) = make_float2(v2, v3);
                } else if (col < N) {
                    Cf[b0i] = v0;
                    Cf[b1i] = v2;
                }
            } else {
                uint32_t h01, l01, h23, l23;
                split2(v0, v1, h01, l01);
                split2(v2, v3, h23, l23);
                long long b0i = (long long)r0 * ldc + col + coff;
                long long b1i = (long long)(r0 + 8) * ldc + col + coff;
                *reinterpret_cast<uint32_t*>(Chi + b0i) = h01;
                *reinterpret_cast<uint32_t*>(Clo + b0i) = l01;
                *reinterpret_cast<uint32_t*>(Chi + b1i) = h23;
                *reinterpret_cast<uint32_t*>(Clo + b1i) = l23;
            }
        }
    }
}

// ---------------- sparsemax: one block per row of 4096; fp32 in, hi/lo bf16 out ----------------
__device__ __forceinline__ float warp_sum(float v) {
    #pragma unroll
    for (int o = 16; o > 0; o >>= 1) v += __shfl_xor_sync(0xffffffffu, v, o);
    return v;
}
__device__ __forceinline__ float warp_max(float v) {
    #pragma unroll
    for (int o = 16; o > 0; o >>= 1) v = fmaxf(v, __shfl_xor_sync(0xffffffffu, v, o));
    return v;
}
__global__ __launch_bounds__(256)
void sparsemax_kernel(const float* __restrict__ S, bf16* __restrict__ Ph, bf16* __restrict__ Pl)
{
    const long long row = blockIdx.x;
    const float4* z4 = reinterpret_cast<const float4*>(S + row * (long long)M_KV);
    const int tid = threadIdx.x;
    float4 v4[4];
    #pragma unroll
    for (int j = 0; j < 4; j++) v4[j] = z4[tid + j * 256];
    float* v = reinterpret_cast<float*>(v4);

    __shared__ float red_s[8];
    __shared__ float red_c[8];
    __shared__ float s_tau, s_delta;

    float m = v[0];
    #pragma unroll
    for (int i = 1; i < 16; i++) m = fmaxf(m, v[i]);
    m = warp_max(m);
    const int w = tid >> 5, lane = tid & 31;
    if (lane == 0) red_s[w] = m;
    __syncthreads();
    if (tid == 0) {
        float mm = red_s[0];
        #pragma unroll
        for (int i = 1; i < 8; i++) mm = fmaxf(mm, red_s[i]);
        s_tau = mm - 1.0f;
    }
    __syncthreads();
    float tau = s_tau;

    for (int it = 0; it < 64; ++it) {
        float s = 0.f, c = 0.f;
        #pragma unroll
        for (int i = 0; i < 16; i++) {
            float d = v[i] - tau;
            if (d > 0.f) { s += d; c += 1.f; }
        }
        s = warp_sum(s); c = warp_sum(c);
        if (lane == 0) { red_s[w] = s; red_c[w] = c; }
        __syncthreads();
        if (tid == 0) {
            float St = 0.f, Ct = 0.f;
            #pragma unroll
            for (int i = 0; i < 8; i++) { St += red_s[i]; Ct += red_c[i]; }
            float delta = (St - 1.0f) / fmaxf(Ct, 1.0f);
            s_tau = tau + delta;
            s_delta = delta;
        }
        __syncthreads();
        tau = s_tau;
        float d = s_delta;
        __syncthreads();
        if (fabsf(d) < 1e-9f) break;
    }

    bf16* ph = Ph + row * (long long)M_KV;
    bf16* pl = Pl + row * (long long)M_KV;
    #pragma unroll
    for (int j = 0; j < 4; j++) {
        float p0 = fmaxf(v[j*4+0] - tau, 0.f), p1 = fmaxf(v[j*4+1] - tau, 0.f);
        float p2 = fmaxf(v[j*4+2] - tau, 0.f), p3 = fmaxf(v[j*4+3] - tau, 0.f);
        uint32_t h01, l01, h23, l23;
        split2(p0, p1, h01, l01);
        split2(p2, p3, h23, l23);
        int o = (tid + j * 256) * 4;
        *reinterpret_cast<uint2*>(ph + o) = make_uint2(h01, h23);
        *reinterpret_cast<uint2*>(pl + o) = make_uint2(l01, l23);
    }
}

// ---------------- prep: fp32 -> hi/lo bf16 ----------------
__global__ __launch_bounds__(256)
void split_convert(const float4* __restrict__ src, uint2* __restrict__ dh,
                   uint2* __restrict__ dl, int n4)
{
    int i = blockIdx.x * 256 + threadIdx.x;
    if (i >= n4) return;
    float4 v = src[i];
    uint32_t h01, l01, h23, l23;
    split2(v.x, v.y, h01, l01);
    split2(v.z, v.w, h23, l23);
    dh[i] = make_uint2(h01, h23);
    dl[i] = make_uint2(l01, l23);
}

// enc -> FIN columns [0, DMODEL)
__global__ __launch_bounds__(256)
void enc_to_fin(const float4* __restrict__ enc, bf16* __restrict__ fh, bf16* __restrict__ fl)
{
    int i = blockIdx.x * 256 + threadIdx.x;           // over N_Q*DMODEL/4
    int row = i >> 8, cg = i & 255;
    float4 v = enc[i];
    uint32_t h01, l01, h23, l23;
    split2(v.x, v.y, h01, l01);
    split2(v.z, v.w, h23, l23);
    int o = row * (2 * DMODEL) + cg * 4;
    *reinterpret_cast<uint2*>(fh + o) = make_uint2(h01, h23);
    *reinterpret_cast<uint2*>(fl + o) = make_uint2(l01, l23);
}

// ---------------- host launcher ----------------
extern "C" void kernel_launch(void* const* d_in, const int* in_sizes, int n_in,
                              void* d_out, int out_size)
{
    const float* enc = (const float*)d_in[0];
    const float* mem = (const float*)d_in[1];
    const float* Wq  = (const float*)d_in[2];
    const float* bq  = (const float*)d_in[3];
    const float* Wk  = (const float*)d_in[4];
    const float* bk  = (const float*)d_in[5];
    const float* Wv  = (const float*)d_in[6];
    const float* bv  = (const float*)d_in[7];
    const float* Wo  = (const float*)d_in[8];
    const float* bo  = (const float*)d_in[9];
    const float* W1  = (const float*)d_in[10];
    const float* b1  = (const float*)d_in[11];
    const float* W2  = (const float*)d_in[12];
    const float* b2  = (const float*)d_in[13];
    float* out = (float*)d_out;

    bf16 *pFINh, *pFINl, *pmemh, *pmeml, *pWqh, *pWql, *pWkh, *pWkl, *pWvh, *pWvl;
    bf16 *pWoh, *pWol, *pW1h, *pW1l, *pW2h, *pW2l;
    bf16 *pQh, *pQl, *pKh, *pKl, *pVh, *pVl, *pPh, *pPl, *pOh, *pOl, *pHh, *pHl;
    float* pS;
    cudaGetSymbolAddress((void**)&pFINh, g_FINh); cudaGetSymbolAddress((void**)&pFINl, g_FINl);
    cudaGetSymbolAddress((void**)&pmemh, g_memh); cudaGetSymbolAddress((void**)&pmeml, g_meml);
    cudaGetSymbolAddress((void**)&pWqh,  g_Wqh);  cudaGetSymbolAddress((void**)&pWql,  g_Wql);
    cudaGetSymbolAddress((void**)&pWkh,  g_Wkh);  cudaGetSymbolAddress((void**)&pWkl,  g_Wkl);
    cudaGetSymbolAddress((void**)&pWvh,  g_Wvh);  cudaGetSymbolAddress((void**)&pWvl,  g_Wvl);
    cudaGetSymbolAddress((void**)&pWoh,  g_Woh);  cudaGetSymbolAddress((void**)&pWol,  g_Wol);
    cudaGetSymbolAddress((void**)&pW1h,  g_W1h);  cudaGetSymbolAddress((void**)&pW1l,  g_W1l);
    cudaGetSymbolAddress((void**)&pW2h,  g_W2h);  cudaGetSymbolAddress((void**)&pW2l,  g_W2l);
    cudaGetSymbolAddress((void**)&pQh,   g_Qh);   cudaGetSymbolAddress((void**)&pQl,   g_Ql);
    cudaGetSymbolAddress((void**)&pKh,   g_Kh);   cudaGetSymbolAddress((void**)&pKl,   g_Kl);
    cudaGetSymbolAddress((void**)&pVh,   g_Vh);   cudaGetSymbolAddress((void**)&pVl,   g_Vl);
    cudaGetSymbolAddress((void**)&pPh,   g_Ph);   cudaGetSymbolAddress((void**)&pPl,   g_Pl);
    cudaGetSymbolAddress((void**)&pOh,   g_Oh);   cudaGetSymbolAddress((void**)&pOl,   g_Ol);
    cudaGetSymbolAddress((void**)&pHh,   g_Hh);   cudaGetSymbolAddress((void**)&pHl,   g_Hl);
    cudaGetSymbolAddress((void**)&pS,    g_S);

    dim3 blk(256);
    auto cvt = [&](const float* s, bf16* h, bf16* l, int n) {
        int n4 = n / 4;
        split_convert<<<(n4 + 255) / 256, blk>>>(
            (const float4*)s, (uint2*)h, (uint2*)l, n4);
    };
    // prep conversions
    cvt(mem, pmemh, pmeml, M_KV * DMODEL);
    cvt(Wq,  pWqh,  pWql,  DMODEL * DMODEL);
    cvt(Wk,  pWkh,  pWkl,  DMODEL * DMODEL);
    cvt(Wv,  pWvh,  pWvl,  DMODEL * DMODEL);
    cvt(Wo,  pWoh,  pWol,  DMODEL * DMODEL);
    cvt(W1,  pW1h,  pW1l,  DFF * 2 * DMODEL);
    cvt(W2,  pW2h,  pW2l,  DOUT * DFF);
    enc_to_fin<<<(N_Q * DMODEL / 4) / 256, blk>>>((const float4*)enc, pFINh, pFINl);

    constexpr int BKP = 40;
    const int DS_MAIN = (2 * 128 * BKP + 2 * 128 * BKP) * 2 * 2;  // 81920
    const int DS_PV   = (2 * 128 * BKP + 2 *  64 * BKP) * 2 * 2;  // 61440

    auto* kSplit = mma_gemm<128,128,64,32,false,1,false,false>;   // proj/Wo: split out + bias
    auto* kRelu  = mma_gemm<128,128,64,32,false,1,true ,false>;   // W1
    auto* kF32   = mma_gemm<128,128,64,32,false,0,false,false>;   // QK -> S
    auto* kOut   = mma_gemm<128,128,64,32,false,0,false,true >;   // W2 -> out (N=1000)
    auto* kPV    = mma_gemm<128, 64,64,16,true ,1,false,false>;   // PV (B=V, NN)
    cudaFuncSetAttribute(kSplit, cudaFuncAttributeMaxDynamicSharedMemorySize, DS_MAIN);
    cudaFuncSetAttribute(kRelu , cudaFuncAttributeMaxDynamicSharedMemorySize, DS_MAIN);
    cudaFuncSetAttribute(kF32  , cudaFuncAttributeMaxDynamicSharedMemorySize, DS_MAIN);
    cudaFuncSetAttribute(kOut  , cudaFuncAttributeMaxDynamicSharedMemorySize, DS_MAIN);
    cudaFuncSetAttribute(kPV   , cudaFuncAttributeMaxDynamicSharedMemorySize, DS_PV);

    // Q = enc @ Wq^T + bq  (A = FIN cols [0,1024), lda 2048)
    kSplit<<<dim3(DMODEL/128, N_Q/128, 1), blk, DS_MAIN>>>(
        N_Q, DMODEL, DMODEL, pFINh, pFINl, 2*DMODEL, 0, pWqh, pWql, DMODEL, 0,
        nullptr, pQh, pQl, DMODEL, 0, bq, 1.0f);
    // K = mem @ Wk^T + bk
    kSplit<<<dim3(DMODEL/128, M_KV/128, 1), blk, DS_MAIN>>>(
        M_KV, DMODEL, DMODEL, pmemh, pmeml, DMODEL, 0, pWkh, pWkl, DMODEL, 0,
        nullptr, pKh, pKl, DMODEL, 0, bk, 1.0f);
    // V = mem @ Wv^T + bv
    kSplit<<<dim3(DMODEL/128, M_KV/128, 1), blk, DS_MAIN>>>(
        M_KV, DMODEL, DMODEL, pmemh, pmeml, DMODEL, 0, pWvh, pWvl, DMODEL, 0,
        nullptr, pVh, pVl, DMODEL, 0, bv, 1.0f);
    // S[h] = (Q_h @ K_h^T) / 32
    kF32<<<dim3(M_KV/128, N_Q/128, NHEADS), blk, DS_MAIN>>>(
        N_Q, M_KV, DHEAD, pQh, pQl, DMODEL, (long long)DHEAD,
        pKh, pKl, DMODEL, (long long)DHEAD,
        pS, nullptr, nullptr, M_KV, (long long)N_Q * M_KV, nullptr, 0.03125f);
    // sparsemax: S -> P hi/lo
    sparsemax_kernel<<<NHEADS * N_Q, blk>>>(pS, pPh, pPl);
    // O_h = P_h @ V_h  (NN; B = V[:, h*64:(h+1)*64])
    kPV<<<dim3(1, N_Q/128, NHEADS), blk, DS_PV>>>(
        N_Q, DHEAD, M_KV, pPh, pPl, M_KV, (long long)N_Q * M_KV,
        pVh, pVl, DMODEL, (long long)DHEAD,
        nullptr, pOh, pOl, DMODEL, (long long)DHEAD, nullptr, 1.0f);
    // FIN[:, 1024:2048] = O @ Wo^T + bo
    kSplit<<<dim3(DMODEL/128, N_Q/128, 1), blk, DS_MAIN>>>(
        N_Q, DMODEL, DMODEL, pOh, pOl, DMODEL, 0, pWoh, pWol, DMODEL, 0,
        nullptr, pFINh + DMODEL, pFINl + DMODEL, 2*DMODEL, 0, bo, 1.0f);
    // H = relu(FIN @ W1^T + b1)
    kRelu<<<dim3(DFF/128, N_Q/128, 1), blk, DS_MAIN>>>(
        N_Q, DFF, 2*DMODEL, pFINh, pFINl, 2*DMODEL, 0, pW1h, pW1l, 2*DMODEL, 0,
        nullptr, pHh, pHl, DFF, 0, b1, 1.0f);
    // OUT = H @ W2^T + b2  (N = 1000)
    kOut<<<dim3((DOUT + 127)/128, N_Q/128, 1), blk, DS_MAIN>>>(
        N_Q, DOUT, DFF, pHh, pHl, DFF, 0, pW2h, pW2l, DFF, 0,
        out, nullptr, nullptr, DOUT, 0, b2, 1.0f);
}

// round 5
// speedup vs baseline: 1.6621x; 1.0072x over previous
#include <cuda_runtime.h>
#include <cuda_bf16.h>
#include <cstdint>
#include <math.h>

// Problem dims (fixed by the dataset)
#define N_Q    2048
#define M_KV   4096
#define DMODEL 1024
#define NHEADS 16
#define DHEAD  64
#define DFF    4096
#define DOUT   1000

typedef __nv_bfloat16 bf16;

// ---------------- scratch (device globals; no allocation allowed) ----------------
__device__ bf16 g_FINh[N_Q * 2 * DMODEL],  g_FINl[N_Q * 2 * DMODEL];
__device__ bf16 g_memh[M_KV * DMODEL],     g_meml[M_KV * DMODEL];
__device__ bf16 g_Wqh[DMODEL * DMODEL],    g_Wql[DMODEL * DMODEL];
__device__ bf16 g_Wkh[DMODEL * DMODEL],    g_Wkl[DMODEL * DMODEL];
__device__ bf16 g_Wvh[DMODEL * DMODEL],    g_Wvl[DMODEL * DMODEL];
__device__ bf16 g_Woh[DMODEL * DMODEL],    g_Wol[DMODEL * DMODEL];
__device__ bf16 g_W1h[DFF * 2 * DMODEL],   g_W1l[DFF * 2 * DMODEL];
__device__ bf16 g_W2h[DOUT * DFF],         g_W2l[DOUT * DFF];
__device__ bf16 g_Qh[N_Q * DMODEL],        g_Ql[N_Q * DMODEL];
__device__ bf16 g_Kh[M_KV * DMODEL],       g_Kl[M_KV * DMODEL];
__device__ bf16 g_Vh[M_KV * DMODEL],       g_Vl[M_KV * DMODEL];
__device__ float g_S[(size_t)NHEADS * N_Q * M_KV];
__device__ float g_tau[NHEADS * N_Q];
__device__ bf16 g_Oh[N_Q * DMODEL],        g_Ol[N_Q * DMODEL];
__device__ bf16 g_Hh[N_Q * DFF],           g_Hl[N_Q * DFF];

// ---------------- helpers ----------------
__device__ __forceinline__ uint32_t smem_u32(const void* p) {
    uint32_t a;
    asm("{ .reg .u64 t; cvta.to.shared.u64 t, %1; cvt.u32.u64 %0, t; }" : "=r"(a) : "l"(p));
    return a;
}
__device__ __forceinline__ void ldmx4(uint32_t* r, uint32_t a) {
    asm volatile("ldmatrix.sync.aligned.m8n8.x4.shared.b16 {%0,%1,%2,%3}, [%4];"
                 : "=r"(r[0]), "=r"(r[1]), "=r"(r[2]), "=r"(r[3]) : "r"(a));
}
__device__ __forceinline__ void mma_bf16(float* d, const uint32_t* a, uint32_t b0, uint32_t b1) {
    asm volatile("mma.sync.aligned.m16n8k16.row.col.f32.bf16.bf16.f32 "
                 "{%0,%1,%2,%3}, {%4,%5,%6,%7}, {%8,%9}, {%0,%1,%2,%3};"
                 : "+f"(d[0]), "+f"(d[1]), "+f"(d[2]), "+f"(d[3])
                 : "r"(a[0]), "r"(a[1]), "r"(a[2]), "r"(a[3]), "r"(b0), "r"(b1));
}
__device__ __forceinline__ void cpa16(uint32_t s, const void* g) {
    asm volatile("cp.async.cg.shared.global [%0], [%1], 16;" :: "r"(s), "l"(g));
}
__device__ __forceinline__ void cpa16z(uint32_t s, const void* g, bool ok) {
    int sz = ok ? 16 : 0;
    asm volatile("cp.async.cg.shared.global [%0], [%1], 16, %2;" :: "r"(s), "l"(g), "r"(sz));
}
#define CPA_COMMIT() asm volatile("cp.async.commit_group;" ::: "memory")
#define CPA_WAIT0()  asm volatile("cp.async.wait_group 0;" ::: "memory")

// split fp32 pair into packed bf16 hi + bf16 residual
__device__ __forceinline__ void split2(float a, float b, uint32_t& h, uint32_t& l) {
    __nv_bfloat162 hh = __floats2bfloat162_rn(a, b);
    float2 hf = __bfloat1622float2(hh);
    __nv_bfloat162 ll = __floats2bfloat162_rn(a - hf.x, b - hf.y);
    h = *reinterpret_cast<uint32_t*>(&hh);
    l = *reinterpret_cast<uint32_t*>(&ll);
}

// ====================== async double-buffered split-bf16 MMA GEMM ======================
// C = alpha * A @ B^T + bias (+ReLU).  A,B pre-split bf16 hi/lo, NT form.
// EPI=0: write fp32 to Cf.  EPI=1: write split hi/lo to Chi/Clo.
template<int BM, int BN, int WM, int WN, int EPI, bool RELU, bool NGUARD>
__global__ __launch_bounds__(256, 2)
void mma_gemm(int M, int N, int K,
              const bf16* __restrict__ Ah, const bf16* __restrict__ Al, int lda, long long sAz,
              const bf16* __restrict__ Bh, const bf16* __restrict__ Bl, int ldb, long long sBz,
              float* __restrict__ Cf, bf16* __restrict__ Chi, bf16* __restrict__ Clo,
              long long ldc, long long sCz,
              const float* __restrict__ bias, float alpha)
{
    constexpr int BK = 32, BKP = 40;               // 80B pitch: 16B-aligned, ldmatrix conflict-free
    constexpr int WNC = BN / WN;
    constexpr int MI = WM / 16, NI2 = WN / 16, NA = WN / 8;
    constexpr int SA = BM * BKP, SB = BN * BKP;    // elements per array per stage
    constexpr int STAGE_BYTES = (2 * SA + 2 * SB) * 2;

    extern __shared__ __align__(16) char smem[];
    const uint32_t uS = smem_u32(smem);

    const int tid = threadIdx.x, wid = tid >> 5, lane = tid & 31;
    Ah += (long long)blockIdx.z * sAz;  Al += (long long)blockIdx.z * sAz;
    Bh += (long long)blockIdx.z * sBz;  Bl += (long long)blockIdx.z * sBz;
    const long long coff = (long long)blockIdx.z * sCz;
    const int row0 = blockIdx.y * BM;
    const int col0 = blockIdx.x * BN;
    const int wm0 = (wid / WNC) * WM;
    const int wn0 = (wid % WNC) * WN;

    float acc[MI][NA][4];
    #pragma unroll
    for (int i = 0; i < MI; i++)
        #pragma unroll
        for (int j = 0; j < NA; j++)
            #pragma unroll
            for (int q = 0; q < 4; q++) acc[i][j][q] = 0.f;

    auto loadT = [&](int stage, int kt) {
        uint32_t base = uS + stage * STAGE_BYTES;
        #pragma unroll
        for (int i = 0; i < (BM * 4) / 256; i++) {
            int ch = tid + i * 256, r = ch >> 2, q = ch & 3;
            cpa16(base + r * 80 + q * 16,            Ah + (size_t)(row0 + r) * lda + kt + q * 8);
            cpa16(base + SA * 2 + r * 80 + q * 16,   Al + (size_t)(row0 + r) * lda + kt + q * 8);
        }
        #pragma unroll
        for (int i = 0; i < (BN * 4) / 256; i++) {
            int ch = tid + i * 256, r = ch >> 2, q = ch & 3;
            bool ok = !NGUARD || (col0 + r) < N;
            cpa16z(base + 2 * SA * 2 + r * 80 + q * 16,
                   Bh + (size_t)(col0 + r) * ldb + kt + q * 8, ok);
            cpa16z(base + (2 * SA + SB) * 2 + r * 80 + q * 16,
                   Bl + (size_t)(col0 + r) * ldb + kt + q * 8, ok);
        }
    };
    auto compute = [&](int stage) {
        uint32_t bA = uS + stage * STAGE_BYTES;
        uint32_t bAh = bA, bAl = bA + SA * 2, bBh = bA + 2 * SA * 2, bBl = bA + (2 * SA + SB) * 2;
        const int lr = lane & 15, lc = (lane >> 4) * 8;
        #pragma unroll
        for (int kk = 0; kk < BK; kk += 16) {
            uint32_t bh[NI2][4], bl[NI2][4];
            #pragma unroll
            for (int ni = 0; ni < NI2; ni++) {
                uint32_t off = (uint32_t)((wn0 + ni * 16 + lr) * 80 + (kk + lc) * 2);
                ldmx4(bh[ni], bBh + off);
                ldmx4(bl[ni], bBl + off);
            }
            #pragma unroll
            for (int mi = 0; mi < MI; mi++) {
                uint32_t ah[4], al[4];
                uint32_t off = (uint32_t)((wm0 + mi * 16 + lr) * 80 + (kk + lc) * 2);
                ldmx4(ah, bAh + off);
                ldmx4(al, bAl + off);
                #pragma unroll
                for (int na = 0; na < NA; na++) {
                    int ni = na >> 1, sel = na & 1;
                    uint32_t b0h = bh[ni][sel], b1h = bh[ni][sel + 2];
                    mma_bf16(acc[mi][na], ah, b0h, b1h);
                    mma_bf16(acc[mi][na], al, b0h, b1h);
                    mma_bf16(acc[mi][na], ah, bl[ni][sel], bl[ni][sel + 2]);
                }
            }
        }
    };

    const int tiles = K / BK;
    loadT(0, 0);
    CPA_COMMIT();
    for (int t = 0; t < tiles; t++) {
        int cur = t & 1;
        CPA_WAIT0();
        __syncthreads();
        if (t + 1 < tiles) loadT((t + 1) & 1, (t + 1) * BK);
        CPA_COMMIT();
        compute(cur);
    }

    // ---------------- epilogue ----------------
    const int lr4 = lane >> 2, lc2 = (lane & 3) * 2;
    #pragma unroll
    for (int mi = 0; mi < MI; mi++) {
        #pragma unroll
        for (int na = 0; na < NA; na++) {
            float* d = acc[mi][na];
            int col = col0 + wn0 + na * 8 + lc2;
            int r0 = row0 + wm0 + mi * 16 + lr4;
            float bb0 = 0.f, bb1 = 0.f;
            if (bias) {
                if (!NGUARD || col     < N) bb0 = bias[col];
                if (!NGUARD || col + 1 < N) bb1 = bias[col + 1];
            }
            float v0 = d[0] * alpha + bb0, v1 = d[1] * alpha + bb1;
            float v2 = d[2] * alpha + bb0, v3 = d[3] * alpha + bb1;
            if (RELU) {
                v0 = fmaxf(v0, 0.f); v1 = fmaxf(v1, 0.f);
                v2 = fmaxf(v2, 0.f); v3 = fmaxf(v3, 0.f);
            }
            if (EPI == 0) {
                long long b0i = (long long)r0 * ldc + col + coff;
                long long b1i = (long long)(r0 + 8) * ldc + col + coff;
                if (!NGUARD || col + 1 < N) {
                    *reinterpret_cast<float2*>(Cf + b0i) = make_float2(v0, v1);
                    *reinterpret_cast<float2*>(Cf + b1i) = make_float2(v2, v3);
                } else if (col < N) {
                    Cf[b0i] = v0;
                    Cf[b1i] = v2;
                }
            } else {
                uint32_t h01, l01, h23, l23;
                split2(v0, v1, h01, l01);
                split2(v2, v3, h23, l23);
                long long b0i = (long long)r0 * ldc + col + coff;
                long long b1i = (long long)(r0 + 8) * ldc + col + coff;
                *reinterpret_cast<uint32_t*>(Chi + b0i) = h01;
                *reinterpret_cast<uint32_t*>(Clo + b0i) = l01;
                *reinterpret_cast<uint32_t*>(Chi + b1i) = h23;
                *reinterpret_cast<uint32_t*>(Clo + b1i) = l23;
            }
        }
    }
}

// ====================== PV: O_h = sparsemax(S_h) @ V_h, tau applied on the fly ======================
__global__ __launch_bounds__(256, 2)
void pv_gemm(const float* __restrict__ S, const float* __restrict__ tau,
             const bf16* __restrict__ Vh, const bf16* __restrict__ Vl,
             bf16* __restrict__ Oh, bf16* __restrict__ Ol)
{
    constexpr int BM = 128, BK = 32, BKP = 40;
    constexpr int SA = BM * BKP, SB = DHEAD * BKP;
    constexpr int STAGE = (2 * SA + 2 * SB) * 2;     // bytes per stage

    extern __shared__ __align__(16) char smem[];
    float* sTau = reinterpret_cast<float*>(smem + 2 * STAGE);

    const int tid = threadIdx.x, wid = tid >> 5, lane = tid & 31;
    const int head = blockIdx.y;
    const int row0 = blockIdx.x * BM;
    const float* Sb  = S + (size_t)head * N_Q * M_KV + (size_t)row0 * M_KV;
    const float* tb  = tau + head * N_Q + row0;
    const bf16* Vhb  = Vh + head * DHEAD;
    const bf16* Vlb  = Vl + head * DHEAD;

    if (tid < BM) sTau[tid] = tb[tid];
    __syncthreads();

    // 2 warps along m (64 each), 4 warps along n (16 each)
    const int wm0 = (wid >> 2) * 64;
    const int wn0 = (wid & 3) * 16;
    constexpr int MI = 4, NA = 2;

    float acc[MI][NA][4];
    #pragma unroll
    for (int i = 0; i < MI; i++)
        #pragma unroll
        for (int j = 0; j < NA; j++)
            #pragma unroll
            for (int q = 0; q < 4; q++) acc[i][j][q] = 0.f;

    float4 aReg[4];
    uint4 bhReg, blReg;
    const int a_r = tid >> 3, a_c = (tid & 7) * 4;
    const int b_k = tid >> 3, b_c = (tid & 7) * 8;

    auto ldRegs = [&](int kt) {
        #pragma unroll
        for (int i = 0; i < 4; i++)
            aReg[i] = *reinterpret_cast<const float4*>(Sb + (size_t)(a_r + i * 32) * M_KV + kt + a_c);
        bhReg = *reinterpret_cast<const uint4*>(Vhb + (size_t)(kt + b_k) * DMODEL + b_c);
        blReg = *reinterpret_cast<const uint4*>(Vlb + (size_t)(kt + b_k) * DMODEL + b_c);
    };
    auto sts = [&](int st) {
        bf16* base = reinterpret_cast<bf16*>(smem + st * STAGE);
        bf16* Ahs = base;
        bf16* Als = base + SA;
        bf16* Bhs = base + 2 * SA;
        bf16* Bls = base + 2 * SA + SB;
        #pragma unroll
        for (int i = 0; i < 4; i++) {
            int r = a_r + i * 32;
            float tv = sTau[r];
            float p0 = fmaxf(aReg[i].x - tv, 0.f), p1 = fmaxf(aReg[i].y - tv, 0.f);
            float p2 = fmaxf(aReg[i].z - tv, 0.f), p3 = fmaxf(aReg[i].w - tv, 0.f);
            uint32_t h01, l01, h23, l23;
            split2(p0, p1, h01, l01);
            split2(p2, p3, h23, l23);
            *reinterpret_cast<uint2*>(Ahs + r * BKP + a_c) = make_uint2(h01, h23);
            *reinterpret_cast<uint2*>(Als + r * BKP + a_c) = make_uint2(l01, l23);
        }
        bf16 th[8], tl[8];
        *reinterpret_cast<uint4*>(th) = bhReg;
        *reinterpret_cast<uint4*>(tl) = blReg;
        #pragma unroll
        for (int j = 0; j < 8; j++) {
            Bhs[(b_c + j) * BKP + b_k] = th[j];
            Bls[(b_c + j) * BKP + b_k] = tl[j];
        }
    };
    auto compute = [&](int st) {
        uint32_t base = smem_u32(smem) + st * STAGE;
        uint32_t uAh = base, uAl = base + SA * 2, uBh = base + 2 * SA * 2, uBl = base + (2 * SA + SB) * 2;
        const int lr = lane & 15, lc = (lane >> 4) * 8;
        #pragma unroll
        for (int kk = 0; kk < BK; kk += 16) {
            uint32_t bh[4], bl[4];
            uint32_t boff = (uint32_t)((wn0 + lr) * BKP + kk + lc) * 2;
            ldmx4(bh, uBh + boff);
            ldmx4(bl, uBl + boff);
            #pragma unroll
            for (int mi = 0; mi < MI; mi++) {
                uint32_t ah[4], al[4];
                uint32_t aoff = (uint32_t)((wm0 + mi * 16 + lr) * BKP + kk + lc) * 2;
                ldmx4(ah, uAh + aoff);
                ldmx4(al, uAl + aoff);
                #pragma unroll
                for (int na = 0; na < NA; na++) {
                    uint32_t b0 = bh[na], b1 = bh[na + 2];
                    mma_bf16(acc[mi][na], ah, b0, b1);
                    mma_bf16(acc[mi][na], al, b0, b1);
                    mma_bf16(acc[mi][na], ah, bl[na], bl[na + 2]);
                }
            }
        }
    };

    const int tiles = M_KV / BK;
    ldRegs(0);
    sts(0);
    for (int t = 0; t < tiles; t++) {
        __syncthreads();
        if (t + 1 < tiles) ldRegs((t + 1) * BK);
        compute(t & 1);
        if (t + 1 < tiles) sts((t + 1) & 1);
    }

    // epilogue: split write to O hi/lo at columns head*64 + ...
    const int lr4 = lane >> 2, lc2 = (lane & 3) * 2;
    #pragma unroll
    for (int mi = 0; mi < MI; mi++) {
        #pragma unroll
        for (int na = 0; na < NA; na++) {
            float* d = acc[mi][na];
            int col = head * DHEAD + wn0 + na * 8 + lc2;
            int r0 = row0 + wm0 + mi * 16 + lr4;
            uint32_t h01, l01, h23, l23;
            split2(d[0], d[1], h01, l01);
            split2(d[2], d[3], h23, l23);
            *reinterpret_cast<uint32_t*>(Oh + (size_t)r0 * DMODEL + col) = h01;
            *reinterpret_cast<uint32_t*>(Ol + (size_t)r0 * DMODEL + col) = l01;
            *reinterpret_cast<uint32_t*>(Oh + (size_t)(r0 + 8) * DMODEL + col) = h23;
            *reinterpret_cast<uint32_t*>(Ol + (size_t)(r0 + 8) * DMODEL + col) = l23;
        }
    }
}

// ---------------- sparsemax tau: one block per row of 4096 ----------------
__device__ __forceinline__ float warp_sum(float v) {
    #pragma unroll
    for (int o = 16; o > 0; o >>= 1) v += __shfl_xor_sync(0xffffffffu, v, o);
    return v;
}
__device__ __forceinline__ float warp_max(float v) {
    #pragma unroll
    for (int o = 16; o > 0; o >>= 1) v = fmaxf(v, __shfl_xor_sync(0xffffffffu, v, o));
    return v;
}
__global__ __launch_bounds__(256)
void sparsemax_tau(const float* __restrict__ S, float* __restrict__ tau)
{
    const long long row = blockIdx.x;
    const float4* z4 = reinterpret_cast<const float4*>(S + row * (long long)M_KV);
    const int tid = threadIdx.x;
    float4 v4[4];
    #pragma unroll
    for (int j = 0; j < 4; j++) v4[j] = z4[tid + j * 256];
    float* v = reinterpret_cast<float*>(v4);

    __shared__ float red_s[8];
    __shared__ float red_c[8];
    __shared__ float s_tau, s_delta;

    float m = v[0];
    #pragma unroll
    for (int i = 1; i < 16; i++) m = fmaxf(m, v[i]);
    m = warp_max(m);
    const int w = tid >> 5, lane = tid & 31;
    if (lane == 0) red_s[w] = m;
    __syncthreads();
    if (tid == 0) {
        float mm = red_s[0];
        #pragma unroll
        for (int i = 1; i < 8; i++) mm = fmaxf(mm, red_s[i]);
        s_tau = mm - 1.0f;
    }
    __syncthreads();
    float t = s_tau;

    for (int it = 0; it < 64; ++it) {
        float s = 0.f, c = 0.f;
        #pragma unroll
        for (int i = 0; i < 16; i++) {
            float d = v[i] - t;
            if (d > 0.f) { s += d; c += 1.f; }
        }
        s = warp_sum(s); c = warp_sum(c);
        if (lane == 0) { red_s[w] = s; red_c[w] = c; }
        __syncthreads();
        if (tid == 0) {
            float St = 0.f, Ct = 0.f;
            #pragma unroll
            for (int i = 0; i < 8; i++) { St += red_s[i]; Ct += red_c[i]; }
            float delta = (St - 1.0f) / fmaxf(Ct, 1.0f);
            s_tau = t + delta;
            s_delta = delta;
        }
        __syncthreads();
        t = s_tau;
        float d = s_delta;
        __syncthreads();
        if (fabsf(d) < 1e-9f) break;
    }
    if (tid == 0) tau[row] = t;
}

// ---------------- prep: fp32 -> hi/lo bf16 ----------------
__global__ __launch_bounds__(256)
void split_convert(const float4* __restrict__ src, uint2* __restrict__ dh,
                   uint2* __restrict__ dl, int n4)
{
    int i = blockIdx.x * 256 + threadIdx.x;
    if (i >= n4) return;
    float4 v = src[i];
    uint32_t h01, l01, h23, l23;
    split2(v.x, v.y, h01, l01);
    split2(v.z, v.w, h23, l23);
    dh[i] = make_uint2(h01, h23);
    dl[i] = make_uint2(l01, l23);
}

// enc -> FIN columns [0, DMODEL)
__global__ __launch_bounds__(256)
void enc_to_fin(const float4* __restrict__ enc, bf16* __restrict__ fh, bf16* __restrict__ fl)
{
    int i = blockIdx.x * 256 + threadIdx.x;           // over N_Q*DMODEL/4
    int row = i >> 8, cg = i & 255;
    float4 v = enc[i];
    uint32_t h01, l01, h23, l23;
    split2(v.x, v.y, h01, l01);
    split2(v.z, v.w, h23, l23);
    int o = row * (2 * DMODEL) + cg * 4;
    *reinterpret_cast<uint2*>(fh + o) = make_uint2(h01, h23);
    *reinterpret_cast<uint2*>(fl + o) = make_uint2(l01, l23);
}

// ---------------- host launcher ----------------
extern "C" void kernel_launch(void* const* d_in, const int* in_sizes, int n_in,
                              void* d_out, int out_size)
{
    const float* enc = (const float*)d_in[0];
    const float* mem = (const float*)d_in[1];
    const float* Wq  = (const float*)d_in[2];
    const float* bq  = (const float*)d_in[3];
    const float* Wk  = (const float*)d_in[4];
    const float* bk  = (const float*)d_in[5];
    const float* Wv  = (const float*)d_in[6];
    const float* bv  = (const float*)d_in[7];
    const float* Wo  = (const float*)d_in[8];
    const float* bo  = (const float*)d_in[9];
    const float* W1  = (const float*)d_in[10];
    const float* b1  = (const float*)d_in[11];
    const float* W2  = (const float*)d_in[12];
    const float* b2  = (const float*)d_in[13];
    float* out = (float*)d_out;

    bf16 *pFINh, *pFINl, *pmemh, *pmeml, *pWqh, *pWql, *pWkh, *pWkl, *pWvh, *pWvl;
    bf16 *pWoh, *pWol, *pW1h, *pW1l, *pW2h, *pW2l;
    bf16 *pQh, *pQl, *pKh, *pKl, *pVh, *pVl, *pOh, *pOl, *pHh, *pHl;
    float *pS, *pTau;
    cudaGetSymbolAddress((void**)&pFINh, g_FINh); cudaGetSymbolAddress((void**)&pFINl, g_FINl);
    cudaGetSymbolAddress((void**)&pmemh, g_memh); cudaGetSymbolAddress((void**)&pmeml, g_meml);
    cudaGetSymbolAddress((void**)&pWqh,  g_Wqh);  cudaGetSymbolAddress((void**)&pWql,  g_Wql);
    cudaGetSymbolAddress((void**)&pWkh,  g_Wkh);  cudaGetSymbolAddress((void**)&pWkl,  g_Wkl);
    cudaGetSymbolAddress((void**)&pWvh,  g_Wvh);  cudaGetSymbolAddress((void**)&pWvl,  g_Wvl);
    cudaGetSymbolAddress((void**)&pWoh,  g_Woh);  cudaGetSymbolAddress((void**)&pWol,  g_Wol);
    cudaGetSymbolAddress((void**)&pW1h,  g_W1h);  cudaGetSymbolAddress((void**)&pW1l,  g_W1l);
    cudaGetSymbolAddress((void**)&pW2h,  g_W2h);  cudaGetSymbolAddress((void**)&pW2l,  g_W2l);
    cudaGetSymbolAddress((void**)&pQh,   g_Qh);   cudaGetSymbolAddress((void**)&pQl,   g_Ql);
    cudaGetSymbolAddress((void**)&pKh,   g_Kh);   cudaGetSymbolAddress((void**)&pKl,   g_Kl);
    cudaGetSymbolAddress((void**)&pVh,   g_Vh);   cudaGetSymbolAddress((void**)&pVl,   g_Vl);
    cudaGetSymbolAddress((void**)&pOh,   g_Oh);   cudaGetSymbolAddress((void**)&pOl,   g_Ol);
    cudaGetSymbolAddress((void**)&pHh,   g_Hh);   cudaGetSymbolAddress((void**)&pHl,   g_Hl);
    cudaGetSymbolAddress((void**)&pS,    g_S);
    cudaGetSymbolAddress((void**)&pTau,  g_tau);

    dim3 blk(256);
    auto cvt = [&](const float* s, bf16* h, bf16* l, int n) {
        int n4 = n / 4;
        split_convert<<<(n4 + 255) / 256, blk>>>(
            (const float4*)s, (uint2*)h, (uint2*)l, n4);
    };
    // prep conversions
    cvt(mem, pmemh, pmeml, M_KV * DMODEL);
    cvt(Wq,  pWqh,  pWql,  DMODEL * DMODEL);
    cvt(Wk,  pWkh,  pWkl,  DMODEL * DMODEL);
    cvt(Wv,  pWvh,  pWvl,  DMODEL * DMODEL);
    cvt(Wo,  pWoh,  pWol,  DMODEL * DMODEL);
    cvt(W1,  pW1h,  pW1l,  DFF * 2 * DMODEL);
    cvt(W2,  pW2h,  pW2l,  DOUT * DFF);
    enc_to_fin<<<(N_Q * DMODEL / 4) / 256, blk>>>((const float4*)enc, pFINh, pFINl);

    constexpr int BKP = 40;
    const int DS_MAIN = (2 * 128 * BKP + 2 * 128 * BKP) * 2 * 2;              // 81920
    const int DS_PV   = (2 * 128 * BKP + 2 * DHEAD * BKP) * 2 * 2 + 512;      // 61952

    auto* kSplit = mma_gemm<128,128,64,32,1,false,false>;   // proj/Wo: split out + bias
    auto* kRelu  = mma_gemm<128,128,64,32,1,true ,false>;   // W1
    auto* kF32   = mma_gemm<128,128,64,32,0,false,false>;   // QK -> S
    auto* kOut   = mma_gemm<128,128,64,32,0,false,true >;   // W2 -> out (N=1000)
    cudaFuncSetAttribute(kSplit, cudaFuncAttributeMaxDynamicSharedMemorySize, DS_MAIN);
    cudaFuncSetAttribute(kRelu , cudaFuncAttributeMaxDynamicSharedMemorySize, DS_MAIN);
    cudaFuncSetAttribute(kF32  , cudaFuncAttributeMaxDynamicSharedMemorySize, DS_MAIN);
    cudaFuncSetAttribute(kOut  , cudaFuncAttributeMaxDynamicSharedMemorySize, DS_MAIN);
    cudaFuncSetAttribute(pv_gemm, cudaFuncAttributeMaxDynamicSharedMemorySize, DS_PV);

    // Q = enc @ Wq^T + bq  (A = FIN cols [0,1024), lda 2048)
    kSplit<<<dim3(DMODEL/128, N_Q/128, 1), blk, DS_MAIN>>>(
        N_Q, DMODEL, DMODEL, pFINh, pFINl, 2*DMODEL, 0, pWqh, pWql, DMODEL, 0,
        nullptr, pQh, pQl, DMODEL, 0, bq, 1.0f);
    // K = mem @ Wk^T + bk
    kSplit<<<dim3(DMODEL/128, M_KV/128, 1), blk, DS_MAIN>>>(
        M_KV, DMODEL, DMODEL, pmemh, pmeml, DMODEL, 0, pWkh, pWkl, DMODEL, 0,
        nullptr, pKh, pKl, DMODEL, 0, bk, 1.0f);
    // V = mem @ Wv^T + bv
    kSplit<<<dim3(DMODEL/128, M_KV/128, 1), blk, DS_MAIN>>>(
        M_KV, DMODEL, DMODEL, pmemh, pmeml, DMODEL, 0, pWvh, pWvl, DMODEL, 0,
        nullptr, pVh, pVl, DMODEL, 0, bv, 1.0f);
    // S[h] = (Q_h @ K_h^T) / 32
    kF32<<<dim3(M_KV/128, N_Q/128, NHEADS), blk, DS_MAIN>>>(
        N_Q, M_KV, DHEAD, pQh, pQl, DMODEL, (long long)DHEAD,
        pKh, pKl, DMODEL, (long long)DHEAD,
        pS, nullptr, nullptr, M_KV, (long long)N_Q * M_KV, nullptr, 0.03125f);
    // sparsemax: S -> tau
    sparsemax_tau<<<NHEADS * N_Q, blk>>>(pS, pTau);
    // O_h = max(S_h - tau, 0) @ V_h
    pv_gemm<<<dim3(N_Q/128, NHEADS), blk, DS_PV>>>(pS, pTau, pVh, pVl, pOh, pOl);
    // FIN[:, 1024:2048] = O @ Wo^T + bo
    kSplit<<<dim3(DMODEL/128, N_Q/128, 1), blk, DS_MAIN>>>(
        N_Q, DMODEL, DMODEL, pOh, pOl, DMODEL, 0, pWoh, pWol, DMODEL, 0,
        nullptr, pFINh + DMODEL, pFINl + DMODEL, 2*DMODEL, 0, bo, 1.0f);
    // H = relu(FIN @ W1^T + b1)
    kRelu<<<dim3(DFF/128, N_Q/128, 1), blk, DS_MAIN>>>(
        N_Q, DFF, 2*DMODEL, pFINh, pFINl, 2*DMODEL, 0, pW1h, pW1l, 2*DMODEL, 0,
        nullptr, pHh, pHl, DFF, 0, b1, 1.0f);
    // OUT = H @ W2^T + b2  (N = 1000)
    kOut<<<dim3((DOUT + 127)/128, N_Q/128, 1), blk, DS_MAIN>>>(
        N_Q, DOUT, DFF, pHh, pHl, DFF, 0, pW2h, pW2l, DFF, 0,
        out, nullptr, nullptr, DOUT, 0, b2, 1.0f);
}

// round 6
// speedup vs baseline: 1.7280x; 1.0396x over previous
#include <cuda_runtime.h>
#include <cuda_bf16.h>
#include <cstdint>
#include <math.h>

// Problem dims (fixed by the dataset)
#define N_Q    2048
#define M_KV   4096
#define DMODEL 1024
#define NHEADS 16
#define DHEAD  64
#define DFF    4096
#define DOUT   1000

typedef __nv_bfloat16 bf16;

// ---------------- scratch (device globals; no allocation allowed) ----------------
__device__ bf16 g_FINh[N_Q * 2 * DMODEL],  g_FINl[N_Q * 2 * DMODEL];
__device__ bf16 g_memh[M_KV * DMODEL],     g_meml[M_KV * DMODEL];
__device__ bf16 g_Wqh[DMODEL * DMODEL],    g_Wql[DMODEL * DMODEL];
__device__ bf16 g_WKVh[2 * DMODEL * DMODEL], g_WKVl[2 * DMODEL * DMODEL];  // [Wk; Wv]
__device__ bf16 g_Woh[DMODEL * DMODEL],    g_Wol[DMODEL * DMODEL];
__device__ bf16 g_W1h[DFF * 2 * DMODEL],   g_W1l[DFF * 2 * DMODEL];
__device__ bf16 g_W2h[DOUT * DFF],         g_W2l[DOUT * DFF];
__device__ bf16 g_Qh[N_Q * DMODEL],        g_Ql[N_Q * DMODEL];
__device__ bf16 g_KVh[M_KV * 2 * DMODEL],  g_KVl[M_KV * 2 * DMODEL];      // K | V
__device__ float g_S[(size_t)NHEADS * N_Q * M_KV];
__device__ float g_tau[NHEADS * N_Q];
__device__ bf16 g_Oh[N_Q * DMODEL],        g_Ol[N_Q * DMODEL];
__device__ bf16 g_Hh[N_Q * DFF],           g_Hl[N_Q * DFF];

// ---------------- helpers ----------------
__device__ __forceinline__ uint32_t smem_u32(const void* p) {
    uint32_t a;
    asm("{ .reg .u64 t; cvta.to.shared.u64 t, %1; cvt.u32.u64 %0, t; }" : "=r"(a) : "l"(p));
    return a;
}
__device__ __forceinline__ void ldmx4(uint32_t* r, uint32_t a) {
    asm volatile("ldmatrix.sync.aligned.m8n8.x4.shared.b16 {%0,%1,%2,%3}, [%4];"
                 : "=r"(r[0]), "=r"(r[1]), "=r"(r[2]), "=r"(r[3]) : "r"(a));
}
__device__ __forceinline__ void mma_bf16(float* d, const uint32_t* a, uint32_t b0, uint32_t b1) {
    asm volatile("mma.sync.aligned.m16n8k16.row.col.f32.bf16.bf16.f32 "
                 "{%0,%1,%2,%3}, {%4,%5,%6,%7}, {%8,%9}, {%0,%1,%2,%3};"
                 : "+f"(d[0]), "+f"(d[1]), "+f"(d[2]), "+f"(d[3])
                 : "r"(a[0]), "r"(a[1]), "r"(a[2]), "r"(a[3]), "r"(b0), "r"(b1));
}
__device__ __forceinline__ void cpa16(uint32_t s, const void* g) {
    asm volatile("cp.async.cg.shared.global [%0], [%1], 16;" :: "r"(s), "l"(g));
}
__device__ __forceinline__ void cpa16z(uint32_t s, const void* g, bool ok) {
    int sz = ok ? 16 : 0;
    asm volatile("cp.async.cg.shared.global [%0], [%1], 16, %2;" :: "r"(s), "l"(g), "r"(sz));
}
#define CPA_COMMIT() asm volatile("cp.async.commit_group;" ::: "memory")
#define CPA_WAIT0()  asm volatile("cp.async.wait_group 0;" ::: "memory")

// split fp32 pair into packed bf16 hi + bf16 residual
__device__ __forceinline__ void split2(float a, float b, uint32_t& h, uint32_t& l) {
    __nv_bfloat162 hh = __floats2bfloat162_rn(a, b);
    float2 hf = __bfloat1622float2(hh);
    __nv_bfloat162 ll = __floats2bfloat162_rn(a - hf.x, b - hf.y);
    h = *reinterpret_cast<uint32_t*>(&hh);
    l = *reinterpret_cast<uint32_t*>(&ll);
}

// ====================== async double-buffered split-bf16 MMA GEMM ======================
// C = alpha * A @ B^T + bias (+ReLU).  A,B pre-split bf16 hi/lo, NT form.
// EPI=0: write fp32 to Cf.  EPI=1: write split hi/lo to Chi/Clo.
// Warp tile 32x64: MI=2, NI2=4, NA=8 -> ldmx/MMA = 0.25
template<int BM, int BN, int WM, int WN, int EPI, bool RELU, bool NGUARD>
__global__ __launch_bounds__(256, 2)
void mma_gemm(int M, int N, int K,
              const bf16* __restrict__ Ah, const bf16* __restrict__ Al, int lda, long long sAz,
              const bf16* __restrict__ Bh, const bf16* __restrict__ Bl, int ldb, long long sBz,
              float* __restrict__ Cf, bf16* __restrict__ Chi, bf16* __restrict__ Clo,
              long long ldc, long long sCz,
              const float* __restrict__ bias, float alpha)
{
    constexpr int BK = 32, BKP = 40;               // 80B pitch: 16B-aligned, ldmatrix conflict-free
    constexpr int WNC = BN / WN;
    constexpr int MI = WM / 16, NI2 = WN / 16, NA = WN / 8;
    constexpr int SA = BM * BKP, SB = BN * BKP;
    constexpr int STAGE_BYTES = (2 * SA + 2 * SB) * 2;

    extern __shared__ __align__(16) char smem[];
    const uint32_t uS = smem_u32(smem);

    const int tid = threadIdx.x, wid = tid >> 5, lane = tid & 31;
    Ah += (long long)blockIdx.z * sAz;  Al += (long long)blockIdx.z * sAz;
    Bh += (long long)blockIdx.z * sBz;  Bl += (long long)blockIdx.z * sBz;
    const long long coff = (long long)blockIdx.z * sCz;
    const int row0 = blockIdx.y * BM;
    const int col0 = blockIdx.x * BN;
    const int wm0 = (wid / WNC) * WM;
    const int wn0 = (wid % WNC) * WN;

    float acc[MI][NA][4];
    #pragma unroll
    for (int i = 0; i < MI; i++)
        #pragma unroll
        for (int j = 0; j < NA; j++)
            #pragma unroll
            for (int q = 0; q < 4; q++) acc[i][j][q] = 0.f;

    auto loadT = [&](int stage, int kt) {
        uint32_t base = uS + stage * STAGE_BYTES;
        #pragma unroll
        for (int i = 0; i < (BM * 4) / 256; i++) {
            int ch = tid + i * 256, r = ch >> 2, q = ch & 3;
            cpa16(base + r * 80 + q * 16,            Ah + (size_t)(row0 + r) * lda + kt + q * 8);
            cpa16(base + SA * 2 + r * 80 + q * 16,   Al + (size_t)(row0 + r) * lda + kt + q * 8);
        }
        #pragma unroll
        for (int i = 0; i < (BN * 4) / 256; i++) {
            int ch = tid + i * 256, r = ch >> 2, q = ch & 3;
            bool ok = !NGUARD || (col0 + r) < N;
            cpa16z(base + 2 * SA * 2 + r * 80 + q * 16,
                   Bh + (size_t)(col0 + r) * ldb + kt + q * 8, ok);
            cpa16z(base + (2 * SA + SB) * 2 + r * 80 + q * 16,
                   Bl + (size_t)(col0 + r) * ldb + kt + q * 8, ok);
        }
    };
    auto compute = [&](int stage) {
        uint32_t bA = uS + stage * STAGE_BYTES;
        uint32_t bAh = bA, bAl = bA + SA * 2, bBh = bA + 2 * SA * 2, bBl = bA + (2 * SA + SB) * 2;
        const int lr = lane & 15, lc = (lane >> 4) * 8;
        #pragma unroll
        for (int kk = 0; kk < BK; kk += 16) {
            uint32_t bh[NI2][4], bl[NI2][4];
            #pragma unroll
            for (int ni = 0; ni < NI2; ni++) {
                uint32_t off = (uint32_t)((wn0 + ni * 16 + lr) * 80 + (kk + lc) * 2);
                ldmx4(bh[ni], bBh + off);
                ldmx4(bl[ni], bBl + off);
            }
            #pragma unroll
            for (int mi = 0; mi < MI; mi++) {
                uint32_t ah[4], al[4];
                uint32_t off = (uint32_t)((wm0 + mi * 16 + lr) * 80 + (kk + lc) * 2);
                ldmx4(ah, bAh + off);
                ldmx4(al, bAl + off);
                #pragma unroll
                for (int na = 0; na < NA; na++) {
                    int ni = na >> 1, sel = na & 1;
                    uint32_t b0h = bh[ni][sel], b1h = bh[ni][sel + 2];
                    mma_bf16(acc[mi][na], ah, b0h, b1h);
                    mma_bf16(acc[mi][na], al, b0h, b1h);
                    mma_bf16(acc[mi][na], ah, bl[ni][sel], bl[ni][sel + 2]);
                }
            }
        }
    };

    const int tiles = K / BK;
    loadT(0, 0);
    CPA_COMMIT();
    for (int t = 0; t < tiles; t++) {
        int cur = t & 1;
        CPA_WAIT0();
        __syncthreads();
        if (t + 1 < tiles) loadT((t + 1) & 1, (t + 1) * BK);
        CPA_COMMIT();
        compute(cur);
    }

    // ---------------- epilogue ----------------
    const int lr4 = lane >> 2, lc2 = (lane & 3) * 2;
    #pragma unroll
    for (int mi = 0; mi < MI; mi++) {
        #pragma unroll
        for (int na = 0; na < NA; na++) {
            float* d = acc[mi][na];
            int col = col0 + wn0 + na * 8 + lc2;
            int r0 = row0 + wm0 + mi * 16 + lr4;
            float bb0 = 0.f, bb1 = 0.f;
            if (bias) {
                if (!NGUARD || col     < N) bb0 = bias[col];
                if (!NGUARD || col + 1 < N) bb1 = bias[col + 1];
            }
            float v0 = d[0] * alpha + bb0, v1 = d[1] * alpha + bb1;
            float v2 = d[2] * alpha + bb0, v3 = d[3] * alpha + bb1;
            if (RELU) {
                v0 = fmaxf(v0, 0.f); v1 = fmaxf(v1, 0.f);
                v2 = fmaxf(v2, 0.f); v3 = fmaxf(v3, 0.f);
            }
            if (EPI == 0) {
                long long b0i = (long long)r0 * ldc + col + coff;
                long long b1i = (long long)(r0 + 8) * ldc + col + coff;
                if (!NGUARD || col + 1 < N) {
                    *reinterpret_cast<float2*>(Cf + b0i) = make_float2(v0, v1);
                    *reinterpret_cast<float2*>(Cf + b1i) = make_float2(v2, v3);
                } else if (col < N) {
                    Cf[b0i] = v0;
                    Cf[b1i] = v2;
                }
            } else {
                uint32_t h01, l01, h23, l23;
                split2(v0, v1, h01, l01);
                split2(v2, v3, h23, l23);
                long long b0i = (long long)r0 * ldc + col + coff;
                long long b1i = (long long)(r0 + 8) * ldc + col + coff;
                *reinterpret_cast<uint32_t*>(Chi + b0i) = h01;
                *reinterpret_cast<uint32_t*>(Clo + b0i) = l01;
                *reinterpret_cast<uint32_t*>(Chi + b1i) = h23;
                *reinterpret_cast<uint32_t*>(Clo + b1i) = l23;
            }
        }
    }
}

// ====================== PV: O_h = sparsemax(S_h) @ V_h, tau applied on the fly ======================
__global__ __launch_bounds__(256, 2)
void pv_gemm(const float* __restrict__ S, const float* __restrict__ tau,
             const bf16* __restrict__ KVh, const bf16* __restrict__ KVl,
             bf16* __restrict__ Oh, bf16* __restrict__ Ol)
{
    constexpr int BM = 128, BK = 32, BKP = 40;
    constexpr int SA = BM * BKP, SB = DHEAD * BKP;
    constexpr int STAGE = (2 * SA + 2 * SB) * 2;

    extern __shared__ __align__(16) char smem[];
    float* sTau = reinterpret_cast<float*>(smem + 2 * STAGE);

    const int tid = threadIdx.x, wid = tid >> 5, lane = tid & 31;
    const int head = blockIdx.y;
    const int row0 = blockIdx.x * BM;
    const float* Sb  = S + (size_t)head * N_Q * M_KV + (size_t)row0 * M_KV;
    const float* tb  = tau + head * N_Q + row0;
    const bf16* Vhb  = KVh + DMODEL + head * DHEAD;   // V half of KV buffer
    const bf16* Vlb  = KVl + DMODEL + head * DHEAD;

    if (tid < BM) sTau[tid] = tb[tid];
    __syncthreads();

    const int wm0 = (wid >> 2) * 64;
    const int wn0 = (wid & 3) * 16;
    constexpr int MI = 4, NA = 2;

    float acc[MI][NA][4];
    #pragma unroll
    for (int i = 0; i < MI; i++)
        #pragma unroll
        for (int j = 0; j < NA; j++)
            #pragma unroll
            for (int q = 0; q < 4; q++) acc[i][j][q] = 0.f;

    float4 aReg[4];
    uint4 bhReg, blReg;
    const int a_r = tid >> 3, a_c = (tid & 7) * 4;
    const int b_k = tid >> 3, b_c = (tid & 7) * 8;

    auto ldRegs = [&](int kt) {
        #pragma unroll
        for (int i = 0; i < 4; i++)
            aReg[i] = *reinterpret_cast<const float4*>(Sb + (size_t)(a_r + i * 32) * M_KV + kt + a_c);
        bhReg = *reinterpret_cast<const uint4*>(Vhb + (size_t)(kt + b_k) * 2 * DMODEL + b_c);
        blReg = *reinterpret_cast<const uint4*>(Vlb + (size_t)(kt + b_k) * 2 * DMODEL + b_c);
    };
    auto sts = [&](int st) {
        bf16* base = reinterpret_cast<bf16*>(smem + st * STAGE);
        bf16* Ahs = base;
        bf16* Als = base + SA;
        bf16* Bhs = base + 2 * SA;
        bf16* Bls = base + 2 * SA + SB;
        #pragma unroll
        for (int i = 0; i < 4; i++) {
            int r = a_r + i * 32;
            float tv = sTau[r];
            float p0 = fmaxf(aReg[i].x - tv, 0.f), p1 = fmaxf(aReg[i].y - tv, 0.f);
            float p2 = fmaxf(aReg[i].z - tv, 0.f), p3 = fmaxf(aReg[i].w - tv, 0.f);
            uint32_t h01, l01, h23, l23;
            split2(p0, p1, h01, l01);
            split2(p2, p3, h23, l23);
            *reinterpret_cast<uint2*>(Ahs + r * BKP + a_c) = make_uint2(h01, h23);
            *reinterpret_cast<uint2*>(Als + r * BKP + a_c) = make_uint2(l01, l23);
        }
        bf16 th[8], tl[8];
        *reinterpret_cast<uint4*>(th) = bhReg;
        *reinterpret_cast<uint4*>(tl) = blReg;
        #pragma unroll
        for (int j = 0; j < 8; j++) {
            Bhs[(b_c + j) * BKP + b_k] = th[j];
            Bls[(b_c + j) * BKP + b_k] = tl[j];
        }
    };
    auto compute = [&](int st) {
        uint32_t base = smem_u32(smem) + st * STAGE;
        uint32_t uAh = base, uAl = base + SA * 2, uBh = base + 2 * SA * 2, uBl = base + (2 * SA + SB) * 2;
        const int lr = lane & 15, lc = (lane >> 4) * 8;
        #pragma unroll
        for (int kk = 0; kk < BK; kk += 16) {
            uint32_t bh[4], bl[4];
            uint32_t boff = (uint32_t)((wn0 + lr) * BKP + kk + lc) * 2;
            ldmx4(bh, uBh + boff);
            ldmx4(bl, uBl + boff);
            #pragma unroll
            for (int mi = 0; mi < MI; mi++) {
                uint32_t ah[4], al[4];
                uint32_t aoff = (uint32_t)((wm0 + mi * 16 + lr) * BKP + kk + lc) * 2;
                ldmx4(ah, uAh + aoff);
                ldmx4(al, uAl + aoff);
                #pragma unroll
                for (int na = 0; na < NA; na++) {
                    uint32_t b0 = bh[na], b1 = bh[na + 2];
                    mma_bf16(acc[mi][na], ah, b0, b1);
                    mma_bf16(acc[mi][na], al, b0, b1);
                    mma_bf16(acc[mi][na], ah, bl[na], bl[na + 2]);
                }
            }
        }
    };

    const int tiles = M_KV / BK;
    ldRegs(0);
    sts(0);
    for (int t = 0; t < tiles; t++) {
        __syncthreads();
        if (t + 1 < tiles) ldRegs((t + 1) * BK);
        compute(t & 1);
        if (t + 1 < tiles) sts((t + 1) & 1);
    }

    const int lr4 = lane >> 2, lc2 = (lane & 3) * 2;
    #pragma unroll
    for (int mi = 0; mi < MI; mi++) {
        #pragma unroll
        for (int na = 0; na < NA; na++) {
            float* d = acc[mi][na];
            int col = head * DHEAD + wn0 + na * 8 + lc2;
            int r0 = row0 + wm0 + mi * 16 + lr4;
            uint32_t h01, l01, h23, l23;
            split2(d[0], d[1], h01, l01);
            split2(d[2], d[3], h23, l23);
            *reinterpret_cast<uint32_t*>(Oh + (size_t)r0 * DMODEL + col) = h01;
            *reinterpret_cast<uint32_t*>(Ol + (size_t)r0 * DMODEL + col) = l01;
            *reinterpret_cast<uint32_t*>(Oh + (size_t)(r0 + 8) * DMODEL + col) = h23;
            *reinterpret_cast<uint32_t*>(Ol + (size_t)(r0 + 8) * DMODEL + col) = l23;
        }
    }
}

// ---------------- sparsemax tau: 4 rows per 256-thread block, 64 threads/row ----------------
__global__ __launch_bounds__(256)
void sparsemax_tau(const float* __restrict__ S, float* __restrict__ tau)
{
    const int tid = threadIdx.x;
    const int grp = tid >> 6;          // row group 0..3
    const int gt  = tid & 63;          // thread within group
    const int lane = tid & 31;
    const int wid = tid >> 5;          // warp 0..7
    const long long row = (long long)blockIdx.x * 4 + grp;

    // each thread: 16 float4 = 64 values, strided across the row
    const float4* z4 = reinterpret_cast<const float4*>(S + row * (long long)M_KV);
    float4 v4[16];
    #pragma unroll
    for (int j = 0; j < 16; j++) v4[j] = z4[gt + j * 64];
    float* v = reinterpret_cast<float*>(v4);

    __shared__ float red_s[8], red_c[8];
    __shared__ float s_tau[4];
    __shared__ int   s_done;

    // row max
    float m = v[0];
    #pragma unroll
    for (int i = 1; i < 64; i++) m = fmaxf(m, v[i]);
    #pragma unroll
    for (int o = 16; o > 0; o >>= 1) m = fmaxf(m, __shfl_xor_sync(0xffffffffu, m, o));
    if (lane == 0) red_s[wid] = m;
    if (tid == 0) s_done = 0;
    __syncthreads();
    if (gt == 0) s_tau[grp] = fmaxf(red_s[grp * 2], red_s[grp * 2 + 1]) - 1.0f;
    __syncthreads();
    float t = s_tau[grp];

    // Newton on f(tau) = sum(max(z - tau, 0)) - 1
    for (int it = 0; it < 64; ++it) {
        float s = 0.f, c = 0.f;
        #pragma unroll
        for (int i = 0; i < 64; i++) {
            float d = v[i] - t;
            if (d > 0.f) { s += d; c += 1.f; }
        }
        #pragma unroll
        for (int o = 16; o > 0; o >>= 1) {
            s += __shfl_xor_sync(0xffffffffu, s, o);
            c += __shfl_xor_sync(0xffffffffu, c, o);
        }
        if (lane == 0) { red_s[wid] = s; red_c[wid] = c; }
        __syncthreads();
        if (gt == 0) {
            float St = red_s[grp * 2] + red_s[grp * 2 + 1];
            float Ct = red_c[grp * 2] + red_c[grp * 2 + 1];
            float delta = (St - 1.0f) / fmaxf(Ct, 1.0f);
            s_tau[grp] = t + delta;
            if (fabsf(delta) >= 1e-9f) atomicOr(&s_done, 1);
        }
        __syncthreads();
        t = s_tau[grp];
        int nd = s_done;
        __syncthreads();
        if (nd == 0) break;
        if (gt == 0) s_done = 0;   // reset for next iter (re-synced at loop top)
        __syncthreads();
    }
    if (gt == 0) tau[row] = t;
}

// ---------------- prep: fp32 -> hi/lo bf16 ----------------
__global__ __launch_bounds__(256)
void split_convert(const float4* __restrict__ src, uint2* __restrict__ dh,
                   uint2* __restrict__ dl, int n4)
{
    int i = blockIdx.x * 256 + threadIdx.x;
    if (i >= n4) return;
    float4 v = src[i];
    uint32_t h01, l01, h23, l23;
    split2(v.x, v.y, h01, l01);
    split2(v.z, v.w, h23, l23);
    dh[i] = make_uint2(h01, h23);
    dl[i] = make_uint2(l01, l23);
}

// enc -> FIN columns [0, DMODEL)
__global__ __launch_bounds__(256)
void enc_to_fin(const float4* __restrict__ enc, bf16* __restrict__ fh, bf16* __restrict__ fl)
{
    int i = blockIdx.x * 256 + threadIdx.x;
    int row = i >> 8, cg = i & 255;
    float4 v = enc[i];
    uint32_t h01, l01, h23, l23;
    split2(v.x, v.y, h01, l01);
    split2(v.z, v.w, h23, l23);
    int o = row * (2 * DMODEL) + cg * 4;
    *reinterpret_cast<uint2*>(fh + o) = make_uint2(h01, h23);
    *reinterpret_cast<uint2*>(fl + o) = make_uint2(l01, l23);
}

// ---------------- host launcher ----------------
extern "C" void kernel_launch(void* const* d_in, const int* in_sizes, int n_in,
                              void* d_out, int out_size)
{
    const float* enc = (const float*)d_in[0];
    const float* mem = (const float*)d_in[1];
    const float* Wq  = (const float*)d_in[2];
    const float* bq  = (const float*)d_in[3];
    const float* Wk  = (const float*)d_in[4];
    const float* bk  = (const float*)d_in[5];
    const float* Wv  = (const float*)d_in[6];
    const float* bv  = (const float*)d_in[7];
    const float* Wo  = (const float*)d_in[8];
    const float* bo  = (const float*)d_in[9];
    const float* W1  = (const float*)d_in[10];
    const float* b1  = (const float*)d_in[11];
    const float* W2  = (const float*)d_in[12];
    const float* b2  = (const float*)d_in[13];
    float* out = (float*)d_out;

    bf16 *pFINh, *pFINl, *pmemh, *pmeml, *pWqh, *pWql, *pWKVh, *pWKVl;
    bf16 *pWoh, *pWol, *pW1h, *pW1l, *pW2h, *pW2l;
    bf16 *pQh, *pQl, *pKVh, *pKVl, *pOh, *pOl, *pHh, *pHl;
    float *pS, *pTau;
    cudaGetSymbolAddress((void**)&pFINh, g_FINh); cudaGetSymbolAddress((void**)&pFINl, g_FINl);
    cudaGetSymbolAddress((void**)&pmemh, g_memh); cudaGetSymbolAddress((void**)&pmeml, g_meml);
    cudaGetSymbolAddress((void**)&pWqh,  g_Wqh);  cudaGetSymbolAddress((void**)&pWql,  g_Wql);
    cudaGetSymbolAddress((void**)&pWKVh, g_WKVh); cudaGetSymbolAddress((void**)&pWKVl, g_WKVl);
    cudaGetSymbolAddress((void**)&pWoh,  g_Woh);  cudaGetSymbolAddress((void**)&pWol,  g_Wol);
    cudaGetSymbolAddress((void**)&pW1h,  g_W1h);  cudaGetSymbolAddress((void**)&pW1l,  g_W1l);
    cudaGetSymbolAddress((void**)&pW2h,  g_W2h);  cudaGetSymbolAddress((void**)&pW2l,  g_W2l);
    cudaGetSymbolAddress((void**)&pQh,   g_Qh);   cudaGetSymbolAddress((void**)&pQl,   g_Ql);
    cudaGetSymbolAddress((void**)&pKVh,  g_KVh);  cudaGetSymbolAddress((void**)&pKVl,  g_KVl);
    cudaGetSymbolAddress((void**)&pOh,   g_Oh);   cudaGetSymbolAddress((void**)&pOl,   g_Ol);
    cudaGetSymbolAddress((void**)&pHh,   g_Hh);   cudaGetSymbolAddress((void**)&pHl,   g_Hl);
    cudaGetSymbolAddress((void**)&pS,    g_S);
    cudaGetSymbolAddress((void**)&pTau,  g_tau);

    dim3 blk(256);
    auto cvt = [&](const float* s, bf16* h, bf16* l, int n) {
        int n4 = n / 4;
        split_convert<<<(n4 + 255) / 256, blk>>>(
            (const float4*)s, (uint2*)h, (uint2*)l, n4);
    };
    // prep conversions
    cvt(mem, pmemh, pmeml, M_KV * DMODEL);
    cvt(Wq,  pWqh,  pWql,  DMODEL * DMODEL);
    cvt(Wk,  pWKVh,                pWKVl,                DMODEL * DMODEL);
    cvt(Wv,  pWKVh + DMODEL*DMODEL, pWKVl + DMODEL*DMODEL, DMODEL * DMODEL);
    cvt(Wo,  pWoh,  pWol,  DMODEL * DMODEL);
    cvt(W1,  pW1h,  pW1l,  DFF * 2 * DMODEL);
    cvt(W2,  pW2h,  pW2l,  DOUT * DFF);
    enc_to_fin<<<(N_Q * DMODEL / 4) / 256, blk>>>((const float4*)enc, pFINh, pFINl);

    constexpr int BKP = 40;
    const int DS_MAIN = (2 * 128 * BKP + 2 * 128 * BKP) * 2 * 2;              // 81920
    const int DS_PV   = (2 * 128 * BKP + 2 * DHEAD * BKP) * 2 * 2 + 512;      // 61952

    auto* kSplit = mma_gemm<128,128,32,64,1,false,false>;   // proj/Wo: split out + bias
    auto* kRelu  = mma_gemm<128,128,32,64,1,true ,false>;   // W1
    auto* kF32   = mma_gemm<128,128,32,64,0,false,false>;   // QK -> S
    auto* kOut   = mma_gemm<128,128,32,64,0,false,true >;   // W2 -> out (N=1000)
    cudaFuncSetAttribute(kSplit, cudaFuncAttributeMaxDynamicSharedMemorySize, DS_MAIN);
    cudaFuncSetAttribute(kRelu , cudaFuncAttributeMaxDynamicSharedMemorySize, DS_MAIN);
    cudaFuncSetAttribute(kF32  , cudaFuncAttributeMaxDynamicSharedMemorySize, DS_MAIN);
    cudaFuncSetAttribute(kOut  , cudaFuncAttributeMaxDynamicSharedMemorySize, DS_MAIN);
    cudaFuncSetAttribute(pv_gemm, cudaFuncAttributeMaxDynamicSharedMemorySize, DS_PV);

    // bias for fused KV proj: bk|bv live separately; pass nullptr and add bias via two
    // separate bias pointers is not possible -> use bias staged per-column by writing
    // a combined bias into constant? Instead: run KV GEMM in two z-batches sharing one launch.
    // z=0: B=Wk, bias=bk, C cols 0..1023 ; z=1: B=Wv, bias=bv, C cols 1024..2047
    // Achieved via sBz = DMODEL*DMODEL (weight stride) and sCz = DMODEL (output col offset),
    // with per-z bias handled by bias pointer stride trick: bias arrays are separate inputs,
    // so instead launch with bias=nullptr and add biases in a tiny epilogue? Simpler: keep
    // two launches for K and V but both write into the combined KV buffer.

    // Q = enc @ Wq^T + bq  (A = FIN cols [0,1024), lda 2048)
    kSplit<<<dim3(DMODEL/128, N_Q/128, 1), blk, DS_MAIN>>>(
        N_Q, DMODEL, DMODEL, pFINh, pFINl, 2*DMODEL, 0, pWqh, pWql, DMODEL, 0,
        nullptr, pQh, pQl, DMODEL, 0, bq, 1.0f);
    // K = mem @ Wk^T + bk -> KV cols [0,1024)
    kSplit<<<dim3(DMODEL/128, M_KV/128, 1), blk, DS_MAIN>>>(
        M_KV, DMODEL, DMODEL, pmemh, pmeml, DMODEL, 0, pWKVh, pWKVl, DMODEL, 0,
        nullptr, pKVh, pKVl, 2*DMODEL, 0, bk, 1.0f);
    // V = mem @ Wv^T + bv -> KV cols [1024,2048)
    kSplit<<<dim3(DMODEL/128, M_KV/128, 1), blk, DS_MAIN>>>(
        M_KV, DMODEL, DMODEL, pmemh, pmeml, DMODEL, 0,
        pWKVh + DMODEL*DMODEL, pWKVl + DMODEL*DMODEL, DMODEL, 0,
        nullptr, pKVh + DMODEL, pKVl + DMODEL, 2*DMODEL, 0, bv, 1.0f);
    // S[h] = (Q_h @ K_h^T) / 32   (K = KV cols [0,1024), ldb 2048)
    kF32<<<dim3(M_KV/128, N_Q/128, NHEADS), blk, DS_MAIN>>>(
        N_Q, M_KV, DHEAD, pQh, pQl, DMODEL, (long long)DHEAD,
        pKVh, pKVl, 2*DMODEL, (long long)DHEAD,
        pS, nullptr, nullptr, M_KV, (long long)N_Q * M_KV, nullptr, 0.03125f);
    // sparsemax: S -> tau  (4 rows per block)
    sparsemax_tau<<<NHEADS * N_Q / 4, blk>>>(pS, pTau);
    // O_h = max(S_h - tau, 0) @ V_h
    pv_gemm<<<dim3(N_Q/128, NHEADS), blk, DS_PV>>>(pS, pTau, pKVh, pKVl, pOh, pOl);
    // FIN[:, 1024:2048] = O @ Wo^T + bo
    kSplit<<<dim3(DMODEL/128, N_Q/128, 1), blk, DS_MAIN>>>(
        N_Q, DMODEL, DMODEL, pOh, pOl, DMODEL, 0, pWoh, pWol, DMODEL, 0,
        nullptr, pFINh + DMODEL, pFINl + DMODEL, 2*DMODEL, 0, bo, 1.0f);
    // H = relu(FIN @ W1^T + b1)
    kRelu<<<dim3(DFF/128, N_Q/128, 1), blk, DS_MAIN>>>(
        N_Q, DFF, 2*DMODEL, pFINh, pFINl, 2*DMODEL, 0, pW1h, pW1l, 2*DMODEL, 0,
        nullptr, pHh, pHl, DFF, 0, b1, 1.0f);
    // OUT = H @ W2^T + b2  (N = 1000)
    kOut<<<dim3((DOUT + 127)/128, N_Q/128, 1), blk, DS_MAIN>>>(
        N_Q, DOUT, DFF, pHh, pHl, DFF, 0, pW2h, pW2l, DFF, 0,
        out, nullptr, nullptr, DOUT, 0, b2, 1.0f);
}